// round 7
// baseline (speedup 1.0000x reference)
#include <cuda_runtime.h>
#include <cuda_bf16.h>
#include <cstdint>

// Problem dims
#define EMBED 512
#define FFN   64
#define NQ    16
#define NTOK  65536   // 16 * 4096

// GEMM tiling
#define MT 64               // tokens per CTA
#define NT 128              // embed outputs per CTA
#define ASTRIDE 272         // smem row stride bytes (256B data + 16B pad)
#define BSTRIDE 272
#define SMEM_A_BYTES (MT * ASTRIDE)          // 17408
#define SMEM_B_BYTES (NT * BSTRIDE)          // 34816
#define SMEM_TOTAL (SMEM_A_BYTES + SMEM_B_BYTES + 512)   // 52736

// H in bf16 split form: per token 128 bf16 = [Hh(64) | Hl(64)], 16 MiB
__device__ __align__(16) __nv_bfloat16 g_hb[(size_t)NTOK * 128];
// W2 in bf16 split form: per e-row 128 bf16 = [Wh(64) | Wl(64)], 128 KiB
__device__ __align__(16) __nv_bfloat16 g_w2b[(size_t)EMBED * 128];

__device__ __forceinline__ uint32_t smem_u32(const void* p) {
    uint32_t a;
    asm("{ .reg .u64 t; cvta.to.shared.u64 t, %1; cvt.u32.u64 %0, t; }"
        : "=r"(a) : "l"(p));
    return a;
}

#define LDSM_X4(r0, r1, r2, r3, addr) \
    asm volatile("ldmatrix.sync.aligned.m8n8.x4.shared.b16 {%0,%1,%2,%3}, [%4];" \
                 : "=r"(r0), "=r"(r1), "=r"(r2), "=r"(r3) : "r"(addr))

#define MMA16816(d, a0, a1, a2, a3, b0, b1) \
    asm volatile("mma.sync.aligned.m16n8k16.row.col.f32.bf16.bf16.f32 " \
                 "{%0,%1,%2,%3}, {%4,%5,%6,%7}, {%8,%9}, {%0,%1,%2,%3};" \
                 : "+f"((d)[0]), "+f"((d)[1]), "+f"((d)[2]), "+f"((d)[3]) \
                 : "r"(a0), "r"(a1), "r"(a2), "r"(a3), "r"(b0), "r"(b1))

#define CP_ASYNC16(dst, src) \
    asm volatile("cp.async.cg.shared.global [%0], [%1], 16;" \
                 :: "r"(dst), "l"(src) : "memory")
#define CP_COMMIT() asm volatile("cp.async.commit_group;" ::: "memory")
#define CP_WAIT0()  asm volatile("cp.async.wait_group 0;" ::: "memory")

// ---------------------------------------------------------------------------
// Kernel W: bf16 two-term split of W2 into g_w2b. One thread per e-row.
// ---------------------------------------------------------------------------
__global__ void __launch_bounds__(128) w2_split_kernel(const float* __restrict__ W2)
{
    int e = blockIdx.x * 128 + threadIdx.x;
    const float4* src = (const float4*)(W2 + (size_t)e * FFN);
    uint32_t hh[32], ll[32];
#pragma unroll
    for (int i = 0; i < 16; i++) {
        float4 v = src[i];
        float f[4] = {v.x, v.y, v.z, v.w};
        uint32_t hb[4], lb[4];
#pragma unroll
        for (int c = 0; c < 4; c++) {
            __nv_bfloat16 h = __float2bfloat16(f[c]);
            __nv_bfloat16 l = __float2bfloat16(f[c] - __bfloat162float(h));
            hb[c] = __bfloat16_as_ushort(h);
            lb[c] = __bfloat16_as_ushort(l);
        }
        hh[2*i]   = hb[0] | (hb[1] << 16);
        hh[2*i+1] = hb[2] | (hb[3] << 16);
        ll[2*i]   = lb[0] | (lb[1] << 16);
        ll[2*i+1] = lb[2] | (lb[3] << 16);
    }
    uint4* dst = (uint4*)(g_w2b + (size_t)e * 128);
#pragma unroll
    for (int i = 0; i < 8; i++)
        dst[i] = make_uint4(hh[4*i], hh[4*i+1], hh[4*i+2], hh[4*i+3]);
#pragma unroll
    for (int i = 0; i < 8; i++)
        dst[8 + i] = make_uint4(ll[4*i], ll[4*i+1], ll[4*i+2], ll[4*i+3]);
}

// ---------------------------------------------------------------------------
// Kernel A: H[t][f] = relu( sum_q cos(x[t][q])*cos(theta[q]) * W1[f][q] + b1[f] )
// 2 threads per token, each computes 32 FFN outputs. Emits bf16 split.
// ---------------------------------------------------------------------------
__global__ void __launch_bounds__(256) h_kernel(
    const float* __restrict__ x,
    const float* __restrict__ theta,
    const float* __restrict__ W1,
    const float* __restrict__ b1)
{
    __shared__ float ct[NQ];
    __shared__ float w1s[FFN * NQ];
    __shared__ float b1s[FFN];

    int tid = threadIdx.x;
    if (tid < NQ) ct[tid] = cosf(theta[tid]);   // 16 precise calls
    for (int i = tid; i < FFN * NQ; i += 256) w1s[i] = W1[i];
    if (tid < FFN) b1s[tid] = b1[tid];
    __syncthreads();

    int t    = blockIdx.x * 128 + (tid >> 1);
    int half = tid & 1;
    const float4* xr = (const float4*)(x + (size_t)t * EMBED);

    float z[NQ];
#pragma unroll
    for (int i = 0; i < 4; i++) {
        float4 v = xr[i];
        z[4*i + 0] = __cosf(v.x) * ct[4*i + 0];
        z[4*i + 1] = __cosf(v.y) * ct[4*i + 1];
        z[4*i + 2] = __cosf(v.z) * ct[4*i + 2];
        z[4*i + 3] = __cosf(v.w) * ct[4*i + 3];
    }

    int fbase = half * 32;
    uint32_t hh[16], hl[16];
#pragma unroll
    for (int p = 0; p < 16; p++) {
        int f0 = fbase + 2 * p;
        float a0 = b1s[f0], a1 = b1s[f0 + 1];
#pragma unroll
        for (int q = 0; q < NQ; q++) {
            a0 = fmaf(z[q], w1s[f0 * NQ + q], a0);
            a1 = fmaf(z[q], w1s[(f0 + 1) * NQ + q], a1);
        }
        a0 = fmaxf(a0, 0.0f);
        a1 = fmaxf(a1, 0.0f);
        __nv_bfloat16 h0 = __float2bfloat16(a0);
        __nv_bfloat16 h1 = __float2bfloat16(a1);
        __nv_bfloat16 l0 = __float2bfloat16(a0 - __bfloat162float(h0));
        __nv_bfloat16 l1 = __float2bfloat16(a1 - __bfloat162float(h1));
        hh[p] = (uint32_t)__bfloat16_as_ushort(h0) | ((uint32_t)__bfloat16_as_ushort(h1) << 16);
        hl[p] = (uint32_t)__bfloat16_as_ushort(l0) | ((uint32_t)__bfloat16_as_ushort(l1) << 16);
    }

    uint4* dH = (uint4*)(g_hb + (size_t)t * 128 + fbase);
    uint4* dL = (uint4*)(g_hb + (size_t)t * 128 + 64 + fbase);
#pragma unroll
    for (int i = 0; i < 4; i++)
        dH[i] = make_uint4(hh[4*i], hh[4*i+1], hh[4*i+2], hh[4*i+3]);
#pragma unroll
    for (int i = 0; i < 4; i++)
        dL[i] = make_uint4(hl[4*i], hl[4*i+1], hl[4*i+2], hl[4*i+3]);
}

// ---------------------------------------------------------------------------
// Kernel B (HMMA): out[t][e] = sum_k H[t][k]*W2[e][k] + b2[e]
// Three-term bf16 split: (Hh,Wh), (Hh,Wl), (Hl,Wh).
// CTA: 128 threads, tile 64 tokens x 128 e, 4 warps (2M x 2N), warp 32x64.
// All operand loads via cp.async from pre-split bf16 buffers. 4 CTAs/SM.
// ---------------------------------------------------------------------------
__global__ void __launch_bounds__(128, 4) gemm_hmma(
    const float* __restrict__ b2,
    float* __restrict__ out)
{
    extern __shared__ char dsm[];
    char* sA   = dsm;                              // [64][272B]:  [Hh|Hl]
    char* sB   = dsm + SMEM_A_BYTES;               // [128][272B]: [Wh|Wl]
    float* b2s = (float*)(dsm + SMEM_A_BYTES + SMEM_B_BYTES);

    uint32_t sAu = smem_u32(sA);
    uint32_t sBu = smem_u32(sB);

    int tid = threadIdx.x;
    int gt0 = blockIdx.x * MT;
    int e0  = blockIdx.y * NT;

    // --- A tile: 64 rows x 256B, 2 threads per row ---
    {
        int row = tid >> 1, half = tid & 1;
        const char* src = (const char*)g_hb + (size_t)(gt0 + row) * 256 + half * 128;
        uint32_t dst = sAu + (uint32_t)row * ASTRIDE + (uint32_t)half * 128;
#pragma unroll
        for (int j = 0; j < 8; j++)
            CP_ASYNC16(dst + j * 16, src + j * 16);
    }
    // --- B tile: 128 rows x 256B, each thread two row-halves ---
    {
#pragma unroll
        for (int rr = 0; rr < 2; rr++) {
            int idx = tid * 2 + rr;
            int row = idx >> 1, half = idx & 1;
            const char* src = (const char*)g_w2b + (size_t)(e0 + row) * 256 + half * 128;
            uint32_t dst = sBu + (uint32_t)row * BSTRIDE + (uint32_t)half * 128;
#pragma unroll
            for (int j = 0; j < 8; j++)
                CP_ASYNC16(dst + j * 16, src + j * 16);
        }
    }
    CP_COMMIT();
    b2s[tid] = b2[e0 + tid];
    CP_WAIT0();
    __syncthreads();

    int wid = tid >> 5, l = tid & 31;
    int wm = wid & 1;        // M block (32 rows)
    int wn = wid >> 1;       // N block (64 cols)

    // Bias-initialized accumulators [mt][nt][4]
    float acc[2][8][4];
    {
        int cb = wn * 64 + (l & 3) * 2;
#pragma unroll
        for (int nt = 0; nt < 8; nt++) {
            float bv0 = b2s[cb + nt * 8];
            float bv1 = b2s[cb + nt * 8 + 1];
#pragma unroll
            for (int mt = 0; mt < 2; mt++) {
                acc[mt][nt][0] = bv0; acc[mt][nt][1] = bv1;
                acc[mt][nt][2] = bv0; acc[mt][nt][3] = bv1;
            }
        }
    }

    // ldmatrix per-lane bases
    uint32_t aBase = sAu + (uint32_t)(wm * 32 + (l & 15)) * ASTRIDE + ((l >> 4) << 4);
    uint32_t bRow  = (uint32_t)(wn * 64 + (l & 7) + ((l >> 4) << 3));
    uint32_t bBase = sBu + bRow * BSTRIDE + (((l >> 3) & 1) << 4);

#pragma unroll
    for (int ks = 0; ks < 12; ks++) {
        int term = ks >> 2;
        int kin  = (ks & 3) * 32;                                  // within 128B block
        uint32_t aOff = (uint32_t)((term == 2 ? 128 : 0) + kin);   // Hh,Hh,Hl
        uint32_t bOff = (uint32_t)((term == 1 ? 128 : 0) + kin);   // Wh,Wl,Wh

        uint32_t a[2][4];
#pragma unroll
        for (int mt = 0; mt < 2; mt++)
            LDSM_X4(a[mt][0], a[mt][1], a[mt][2], a[mt][3],
                    aBase + (uint32_t)(mt * 16) * ASTRIDE + aOff);

        uint32_t b[8][2];
#pragma unroll
        for (int j = 0; j < 4; j++) {
            uint32_t r0, r1, r2, r3;
            LDSM_X4(r0, r1, r2, r3,
                    bBase + (uint32_t)(j * 16) * BSTRIDE + bOff);
            b[2*j][0]   = r0;  b[2*j][1]   = r1;
            b[2*j+1][0] = r2;  b[2*j+1][1] = r3;
        }

#pragma unroll
        for (int mt = 0; mt < 2; mt++)
#pragma unroll
            for (int nt = 0; nt < 8; nt++)
                MMA16816(acc[mt][nt], a[mt][0], a[mt][1], a[mt][2], a[mt][3],
                         b[nt][0], b[nt][1]);
    }

    // Epilogue: direct coalesced float2 stores
    {
        int row_l = (l >> 2);
        int col_l = (l & 3) * 2;
#pragma unroll
        for (int mt = 0; mt < 2; mt++) {
            int r0 = gt0 + wm * 32 + mt * 16 + row_l;
            float* o0 = out + (size_t)r0 * EMBED + e0 + wn * 64 + col_l;
            float* o1 = out + (size_t)(r0 + 8) * EMBED + e0 + wn * 64 + col_l;
#pragma unroll
            for (int nt = 0; nt < 8; nt++) {
                *(float2*)(o0 + nt * 8) = make_float2(acc[mt][nt][0], acc[mt][nt][1]);
                *(float2*)(o1 + nt * 8) = make_float2(acc[mt][nt][2], acc[mt][nt][3]);
            }
        }
    }
}

// ---------------------------------------------------------------------------
extern "C" void kernel_launch(void* const* d_in, const int* in_sizes, int n_in,
                              void* d_out, int out_size)
{
    const float *x = nullptr, *theta = nullptr, *W1 = nullptr,
                *b1 = nullptr, *W2 = nullptr, *b2 = nullptr;
    for (int i = 0; i < n_in; i++) {
        switch (in_sizes[i]) {
            case NTOK * EMBED: x     = (const float*)d_in[i]; break;
            case NQ:           theta = (const float*)d_in[i]; break;
            case FFN * NQ:     W1    = (const float*)d_in[i]; break;
            case FFN:          b1    = (const float*)d_in[i]; break;
            case EMBED * FFN:  W2    = (const float*)d_in[i]; break;
            case EMBED:        b2    = (const float*)d_in[i]; break;
            default: break;
        }
    }
    float* out = (float*)d_out;

    static int smem_set = 0;
    if (!smem_set) {
        cudaFuncSetAttribute(gemm_hmma,
                             cudaFuncAttributeMaxDynamicSharedMemorySize,
                             SMEM_TOTAL);
        smem_set = 1;
    }

    w2_split_kernel<<<EMBED / 128, 128>>>(W2);
    h_kernel<<<NTOK / 128, 256>>>(x, theta, W1, b1);
    gemm_hmma<<<dim3(NTOK / MT, EMBED / NT), 128, SMEM_TOTAL>>>(b2, out);
}

// round 8
// speedup vs baseline: 1.1938x; 1.1938x over previous
#include <cuda_runtime.h>
#include <cuda_bf16.h>
#include <cstdint>

// Problem dims
#define EMBED 512
#define FFN   64
#define NQ    16
#define NTOK  65536   // 16 * 4096

// GEMM tiling (R5-proven shape)
#define MT 128              // tokens per CTA
#define NT 128              // embed outputs per CTA
#define ASTRIDE 272         // smem row stride bytes (256B data + 16B pad)
#define BSTRIDE 272
#define SMEM_A_BYTES (MT * ASTRIDE)          // 34816
#define SMEM_B_BYTES (NT * BSTRIDE)          // 34816
#define SMEM_TOTAL (SMEM_A_BYTES + SMEM_B_BYTES + 512)   // 70144

// H in bf16 split form: per token 128 bf16 = [Hh(64) | Hl(64)], 16 MiB
__device__ __align__(16) __nv_bfloat16 g_hb[(size_t)NTOK * 128];
// W2 in bf16 split form: per e-row 128 bf16 = [Wh(64) | Wl(64)], 128 KiB
__device__ __align__(16) __nv_bfloat16 g_w2b[(size_t)EMBED * 128];

__device__ __forceinline__ uint32_t smem_u32(const void* p) {
    uint32_t a;
    asm("{ .reg .u64 t; cvta.to.shared.u64 t, %1; cvt.u32.u64 %0, t; }"
        : "=r"(a) : "l"(p));
    return a;
}

#define LDSM_X4(r0, r1, r2, r3, addr) \
    asm volatile("ldmatrix.sync.aligned.m8n8.x4.shared.b16 {%0,%1,%2,%3}, [%4];" \
                 : "=r"(r0), "=r"(r1), "=r"(r2), "=r"(r3) : "r"(addr))

#define MMA16816(d, a0, a1, a2, a3, b0, b1) \
    asm volatile("mma.sync.aligned.m16n8k16.row.col.f32.bf16.bf16.f32 " \
                 "{%0,%1,%2,%3}, {%4,%5,%6,%7}, {%8,%9}, {%0,%1,%2,%3};" \
                 : "+f"((d)[0]), "+f"((d)[1]), "+f"((d)[2]), "+f"((d)[3]) \
                 : "r"(a0), "r"(a1), "r"(a2), "r"(a3), "r"(b0), "r"(b1))

#define CP_ASYNC16(dst, src) \
    asm volatile("cp.async.cg.shared.global [%0], [%1], 16;" \
                 :: "r"(dst), "l"(src) : "memory")
#define CP_COMMIT() asm volatile("cp.async.commit_group;" ::: "memory")
#define CP_WAIT0()  asm volatile("cp.async.wait_group 0;" ::: "memory")

// ---------------------------------------------------------------------------
// Kernel A: H[t][f] = relu( sum_q cos(x[t][q])*cos(theta[q]) * W1[f][q] + b1[f] )
// 2 threads per token, each computes 32 FFN outputs. Emits bf16 split to g_hb.
// Block 0 additionally bf16-splits W2 into g_w2b (2 e-rows per thread).
// ---------------------------------------------------------------------------
__global__ void __launch_bounds__(256) h_kernel(
    const float* __restrict__ x,
    const float* __restrict__ theta,
    const float* __restrict__ W1,
    const float* __restrict__ b1,
    const float* __restrict__ W2)
{
    __shared__ float ct[NQ];
    __shared__ float w1s[FFN * NQ];
    __shared__ float b1s[FFN];

    int tid = threadIdx.x;
    if (tid < NQ) ct[tid] = cosf(theta[tid]);   // 16 precise calls
    for (int i = tid; i < FFN * NQ; i += 256) w1s[i] = W1[i];
    if (tid < FFN) b1s[tid] = b1[tid];
    __syncthreads();

    // Block 0 side-job: split W2 (512 rows, 2 per thread)
    if (blockIdx.x == 0) {
#pragma unroll
        for (int rr = 0; rr < 2; rr++) {
            int e = tid + rr * 256;
            const float4* src = (const float4*)(W2 + (size_t)e * FFN);
            uint32_t hh[32], ll[32];
#pragma unroll
            for (int i = 0; i < 16; i++) {
                float4 v = src[i];
                float f[4] = {v.x, v.y, v.z, v.w};
                uint32_t hb[4], lb[4];
#pragma unroll
                for (int c = 0; c < 4; c++) {
                    __nv_bfloat16 h = __float2bfloat16(f[c]);
                    __nv_bfloat16 l = __float2bfloat16(f[c] - __bfloat162float(h));
                    hb[c] = __bfloat16_as_ushort(h);
                    lb[c] = __bfloat16_as_ushort(l);
                }
                hh[2*i]   = hb[0] | (hb[1] << 16);
                hh[2*i+1] = hb[2] | (hb[3] << 16);
                ll[2*i]   = lb[0] | (lb[1] << 16);
                ll[2*i+1] = lb[2] | (lb[3] << 16);
            }
            uint4* dst = (uint4*)(g_w2b + (size_t)e * 128);
#pragma unroll
            for (int i = 0; i < 8; i++)
                dst[i] = make_uint4(hh[4*i], hh[4*i+1], hh[4*i+2], hh[4*i+3]);
#pragma unroll
            for (int i = 0; i < 8; i++)
                dst[8 + i] = make_uint4(ll[4*i], ll[4*i+1], ll[4*i+2], ll[4*i+3]);
        }
    }

    int t    = blockIdx.x * 128 + (tid >> 1);
    int half = tid & 1;
    const float4* xr = (const float4*)(x + (size_t)t * EMBED);

    float z[NQ];
#pragma unroll
    for (int i = 0; i < 4; i++) {
        float4 v = xr[i];
        z[4*i + 0] = __cosf(v.x) * ct[4*i + 0];
        z[4*i + 1] = __cosf(v.y) * ct[4*i + 1];
        z[4*i + 2] = __cosf(v.z) * ct[4*i + 2];
        z[4*i + 3] = __cosf(v.w) * ct[4*i + 3];
    }

    int fbase = half * 32;
    uint32_t hh[16], hl[16];
#pragma unroll
    for (int p = 0; p < 16; p++) {
        int f0 = fbase + 2 * p;
        float a0 = b1s[f0], a1 = b1s[f0 + 1];
#pragma unroll
        for (int q = 0; q < NQ; q++) {
            a0 = fmaf(z[q], w1s[f0 * NQ + q], a0);
            a1 = fmaf(z[q], w1s[(f0 + 1) * NQ + q], a1);
        }
        a0 = fmaxf(a0, 0.0f);
        a1 = fmaxf(a1, 0.0f);
        __nv_bfloat16 h0 = __float2bfloat16(a0);
        __nv_bfloat16 h1 = __float2bfloat16(a1);
        __nv_bfloat16 l0 = __float2bfloat16(a0 - __bfloat162float(h0));
        __nv_bfloat16 l1 = __float2bfloat16(a1 - __bfloat162float(h1));
        hh[p] = (uint32_t)__bfloat16_as_ushort(h0) | ((uint32_t)__bfloat16_as_ushort(h1) << 16);
        hl[p] = (uint32_t)__bfloat16_as_ushort(l0) | ((uint32_t)__bfloat16_as_ushort(l1) << 16);
    }

    uint4* dH = (uint4*)(g_hb + (size_t)t * 128 + fbase);
    uint4* dL = (uint4*)(g_hb + (size_t)t * 128 + 64 + fbase);
#pragma unroll
    for (int i = 0; i < 4; i++)
        dH[i] = make_uint4(hh[4*i], hh[4*i+1], hh[4*i+2], hh[4*i+3]);
#pragma unroll
    for (int i = 0; i < 4; i++)
        dL[i] = make_uint4(hl[4*i], hl[4*i+1], hl[4*i+2], hl[4*i+3]);
}

// ---------------------------------------------------------------------------
// Kernel B (HMMA): out[t][e] = sum_k H[t][k]*W2[e][k] + b2[e]
// Three-term bf16 split: (Hh,Wh), (Hh,Wl), (Hl,Wh).
// CTA: 256 threads, tile 128 tokens x 128 e, 8 warps (4M x 2N), warp 32x64.
// Tile loads: pure cp.async from pre-split g_hb / g_w2b. 2 CTAs/SM.
// ---------------------------------------------------------------------------
__global__ void __launch_bounds__(256, 2) gemm_hmma(
    const float* __restrict__ b2,
    float* __restrict__ out)
{
    extern __shared__ char dsm[];
    char* sA   = dsm;                              // [128][272B]: [Hh|Hl]
    char* sB   = dsm + SMEM_A_BYTES;               // [128][272B]: [Wh|Wl]
    float* b2s = (float*)(dsm + SMEM_A_BYTES + SMEM_B_BYTES);

    uint32_t sAu = smem_u32(sA);
    uint32_t sBu = smem_u32(sB);

    int tid = threadIdx.x;
    int gt0 = blockIdx.x * MT;
    int e0  = blockIdx.y * NT;

    // --- A tile: 128 rows x 256B, 2 threads per row, 8x cp.async 16B ---
    {
        int row = tid >> 1, half = tid & 1;
        const char* src = (const char*)g_hb + (size_t)(gt0 + row) * 256 + half * 128;
        uint32_t dst = sAu + (uint32_t)row * ASTRIDE + (uint32_t)half * 128;
#pragma unroll
        for (int j = 0; j < 8; j++)
            CP_ASYNC16(dst + j * 16, src + j * 16);
    }
    // --- B tile: 128 rows x 256B, 2 threads per row ---
    {
        int row = tid >> 1, half = tid & 1;
        const char* src = (const char*)g_w2b + (size_t)(e0 + row) * 256 + half * 128;
        uint32_t dst = sBu + (uint32_t)row * BSTRIDE + (uint32_t)half * 128;
#pragma unroll
        for (int j = 0; j < 8; j++)
            CP_ASYNC16(dst + j * 16, src + j * 16);
    }
    CP_COMMIT();
    if (tid < NT) b2s[tid] = b2[e0 + tid];
    CP_WAIT0();
    __syncthreads();

    int wid = tid >> 5, l = tid & 31;
    int wm = wid & 3;        // M block (32 rows)
    int wn = wid >> 2;       // N block (64 cols)

    // Bias-initialized accumulators [mt][nt][4]
    float acc[2][8][4];
    {
        int cb = wn * 64 + (l & 3) * 2;
#pragma unroll
        for (int nt = 0; nt < 8; nt++) {
            float bv0 = b2s[cb + nt * 8];
            float bv1 = b2s[cb + nt * 8 + 1];
#pragma unroll
            for (int mt = 0; mt < 2; mt++) {
                acc[mt][nt][0] = bv0; acc[mt][nt][1] = bv1;
                acc[mt][nt][2] = bv0; acc[mt][nt][3] = bv1;
            }
        }
    }

    // ldmatrix per-lane bases
    uint32_t aBase = sAu + (uint32_t)(wm * 32 + (l & 15)) * ASTRIDE + ((l >> 4) << 4);
    uint32_t bRow  = (uint32_t)(wn * 64 + (l & 7) + ((l >> 4) << 3));
    uint32_t bBase = sBu + bRow * BSTRIDE + (((l >> 3) & 1) << 4);

#pragma unroll
    for (int ks = 0; ks < 12; ks++) {
        int term = ks >> 2;
        int kin  = (ks & 3) * 32;                                  // within 128B block
        uint32_t aOff = (uint32_t)((term == 2 ? 128 : 0) + kin);   // Hh,Hh,Hl
        uint32_t bOff = (uint32_t)((term == 1 ? 128 : 0) + kin);   // Wh,Wl,Wh

        uint32_t a[2][4];
#pragma unroll
        for (int mt = 0; mt < 2; mt++)
            LDSM_X4(a[mt][0], a[mt][1], a[mt][2], a[mt][3],
                    aBase + (uint32_t)(mt * 16) * ASTRIDE + aOff);

        uint32_t b[8][2];
#pragma unroll
        for (int j = 0; j < 4; j++) {
            uint32_t r0, r1, r2, r3;
            LDSM_X4(r0, r1, r2, r3,
                    bBase + (uint32_t)(j * 16) * BSTRIDE + bOff);
            b[2*j][0]   = r0;  b[2*j][1]   = r1;
            b[2*j+1][0] = r2;  b[2*j+1][1] = r3;
        }

#pragma unroll
        for (int mt = 0; mt < 2; mt++)
#pragma unroll
            for (int nt = 0; nt < 8; nt++)
                MMA16816(acc[mt][nt], a[mt][0], a[mt][1], a[mt][2], a[mt][3],
                         b[nt][0], b[nt][1]);
    }

    // Epilogue: direct coalesced float2 stores
    {
        int row_l = (l >> 2);
        int col_l = (l & 3) * 2;
#pragma unroll
        for (int mt = 0; mt < 2; mt++) {
            int r0 = gt0 + wm * 32 + mt * 16 + row_l;
            float* o0 = out + (size_t)r0 * EMBED + e0 + wn * 64 + col_l;
            float* o1 = out + (size_t)(r0 + 8) * EMBED + e0 + wn * 64 + col_l;
#pragma unroll
            for (int nt = 0; nt < 8; nt++) {
                *(float2*)(o0 + nt * 8) = make_float2(acc[mt][nt][0], acc[mt][nt][1]);
                *(float2*)(o1 + nt * 8) = make_float2(acc[mt][nt][2], acc[mt][nt][3]);
            }
        }
    }
}

// ---------------------------------------------------------------------------
extern "C" void kernel_launch(void* const* d_in, const int* in_sizes, int n_in,
                              void* d_out, int out_size)
{
    const float *x = nullptr, *theta = nullptr, *W1 = nullptr,
                *b1 = nullptr, *W2 = nullptr, *b2 = nullptr;
    for (int i = 0; i < n_in; i++) {
        switch (in_sizes[i]) {
            case NTOK * EMBED: x     = (const float*)d_in[i]; break;
            case NQ:           theta = (const float*)d_in[i]; break;
            case FFN * NQ:     W1    = (const float*)d_in[i]; break;
            case FFN:          b1    = (const float*)d_in[i]; break;
            case EMBED * FFN:  W2    = (const float*)d_in[i]; break;
            case EMBED:        b2    = (const float*)d_in[i]; break;
            default: break;
        }
    }
    float* out = (float*)d_out;

    static int smem_set = 0;
    if (!smem_set) {
        cudaFuncSetAttribute(gemm_hmma,
                             cudaFuncAttributeMaxDynamicSharedMemorySize,
                             SMEM_TOTAL);
        smem_set = 1;
    }

    h_kernel<<<NTOK / 128, 256>>>(x, theta, W1, b1, W2);
    gemm_hmma<<<dim3(NTOK / MT, EMBED / NT), 256, SMEM_TOTAL>>>(b2, out);
}

// round 10
// speedup vs baseline: 1.2604x; 1.0558x over previous
#include <cuda_runtime.h>
#include <cuda_bf16.h>
#include <cstdint>

// Problem dims
#define EMBED 512
#define FFN   64
#define NQ    16
#define NTOK  65536   // 16 * 4096

// GEMM tiling
#define MT 128              // tokens per CTA
#define NT 128              // embed outputs per CTA
#define ASTRIDE 272         // smem row stride bytes (256B data + 16B pad)
#define BSTRIDE 272
#define SMEM_A_BYTES (MT * ASTRIDE)          // 34816
#define SMEM_B_BYTES (NT * BSTRIDE)          // 34816
#define SMEM_TOTAL (SMEM_A_BYTES + SMEM_B_BYTES + 512)   // 70144

// H in bf16 split form: per token 128 bf16 = [Hh(64) | Hl(64)], 16 MiB
__device__ __align__(16) __nv_bfloat16 g_hb[(size_t)NTOK * 128];
// W2 in bf16 split form: per e-row 128 bf16 = [Wh(64) | Wl(64)], 128 KiB
__device__ __align__(16) __nv_bfloat16 g_w2b[(size_t)EMBED * 128];

__device__ __forceinline__ uint32_t smem_u32(const void* p) {
    uint32_t a;
    asm("{ .reg .u64 t; cvta.to.shared.u64 t, %1; cvt.u32.u64 %0, t; }"
        : "=r"(a) : "l"(p));
    return a;
}

#define LDSM_X4(r0, r1, r2, r3, addr) \
    asm volatile("ldmatrix.sync.aligned.m8n8.x4.shared.b16 {%0,%1,%2,%3}, [%4];" \
                 : "=r"(r0), "=r"(r1), "=r"(r2), "=r"(r3) : "r"(addr))

#define MMA16816(d, a0, a1, a2, a3, b0, b1) \
    asm volatile("mma.sync.aligned.m16n8k16.row.col.f32.bf16.bf16.f32 " \
                 "{%0,%1,%2,%3}, {%4,%5,%6,%7}, {%8,%9}, {%0,%1,%2,%3};" \
                 : "+f"((d)[0]), "+f"((d)[1]), "+f"((d)[2]), "+f"((d)[3]) \
                 : "r"(a0), "r"(a1), "r"(a2), "r"(a3), "r"(b0), "r"(b1))

// ---------------------------------------------------------------------------
// Kernel A: H[t][f] = relu( sum_q cos(x[t][q])*cos(theta[q]) * W1[f][q] + b1[f] )
// 1 thread per token, 16 groups x 4 concurrent FMA chains (all 64 outputs).
// Emits bf16 split to g_hb: [Hh(64) | Hl(64)].
// Block 0 additionally bf16-splits W2 into g_w2b (4 e-rows per thread).
// ---------------------------------------------------------------------------
__global__ void __launch_bounds__(128) h_kernel(
    const float* __restrict__ x,
    const float* __restrict__ theta,
    const float* __restrict__ W1,
    const float* __restrict__ b1,
    const float* __restrict__ W2)
{
    __shared__ float ct[NQ];
    __shared__ float w1s[FFN * NQ];
    __shared__ float b1s[FFN];

    int tid = threadIdx.x;
    if (tid < NQ) ct[tid] = cosf(theta[tid]);   // 16 precise calls
    for (int i = tid; i < FFN * NQ; i += 128) w1s[i] = W1[i];
    if (tid < FFN) b1s[tid] = b1[tid];
    __syncthreads();

    // Block 0 side-job: split W2 (512 rows, 4 per thread)
    if (blockIdx.x == 0) {
#pragma unroll
        for (int rr = 0; rr < 4; rr++) {
            int e = tid + rr * 128;
            const float4* src = (const float4*)(W2 + (size_t)e * FFN);
            uint32_t hh[32], ll[32];
#pragma unroll
            for (int i = 0; i < 16; i++) {
                float4 v = src[i];
                float f[4] = {v.x, v.y, v.z, v.w};
                uint32_t hb[4], lb[4];
#pragma unroll
                for (int c = 0; c < 4; c++) {
                    __nv_bfloat16 h = __float2bfloat16(f[c]);
                    __nv_bfloat16 l = __float2bfloat16(f[c] - __bfloat162float(h));
                    hb[c] = __bfloat16_as_ushort(h);
                    lb[c] = __bfloat16_as_ushort(l);
                }
                hh[2*i]   = hb[0] | (hb[1] << 16);
                hh[2*i+1] = hb[2] | (hb[3] << 16);
                ll[2*i]   = lb[0] | (lb[1] << 16);
                ll[2*i+1] = lb[2] | (lb[3] << 16);
            }
            uint4* dst = (uint4*)(g_w2b + (size_t)e * 128);
#pragma unroll
            for (int i = 0; i < 8; i++)
                dst[i] = make_uint4(hh[4*i], hh[4*i+1], hh[4*i+2], hh[4*i+3]);
#pragma unroll
            for (int i = 0; i < 8; i++)
                dst[8 + i] = make_uint4(ll[4*i], ll[4*i+1], ll[4*i+2], ll[4*i+3]);
        }
    }

    int t = blockIdx.x * 128 + tid;
    const float4* xr = (const float4*)(x + (size_t)t * EMBED);

    float z[NQ];
#pragma unroll
    for (int i = 0; i < 4; i++) {
        float4 v = xr[i];
        z[4*i + 0] = __cosf(v.x) * ct[4*i + 0];
        z[4*i + 1] = __cosf(v.y) * ct[4*i + 1];
        z[4*i + 2] = __cosf(v.z) * ct[4*i + 2];
        z[4*i + 3] = __cosf(v.w) * ct[4*i + 3];
    }

    uint32_t hh[32], hl[32];
#pragma unroll
    for (int g = 0; g < 16; g++) {          // 16 groups x 4 chains = 64 outputs
        int f0 = 4 * g;
        float a0 = b1s[f0], a1 = b1s[f0+1], a2 = b1s[f0+2], a3 = b1s[f0+3];
#pragma unroll
        for (int q = 0; q < NQ; q++) {
            float zq = z[q];
            a0 = fmaf(zq, w1s[(f0+0) * NQ + q], a0);
            a1 = fmaf(zq, w1s[(f0+1) * NQ + q], a1);
            a2 = fmaf(zq, w1s[(f0+2) * NQ + q], a2);
            a3 = fmaf(zq, w1s[(f0+3) * NQ + q], a3);
        }
        float s[4] = { fmaxf(a0, 0.0f), fmaxf(a1, 0.0f),
                       fmaxf(a2, 0.0f), fmaxf(a3, 0.0f) };
        uint32_t hb[4], lb[4];
#pragma unroll
        for (int c = 0; c < 4; c++) {
            __nv_bfloat16 h = __float2bfloat16(s[c]);
            __nv_bfloat16 l = __float2bfloat16(s[c] - __bfloat162float(h));
            hb[c] = __bfloat16_as_ushort(h);
            lb[c] = __bfloat16_as_ushort(l);
        }
        hh[2*g]   = hb[0] | (hb[1] << 16);
        hh[2*g+1] = hb[2] | (hb[3] << 16);
        hl[2*g]   = lb[0] | (lb[1] << 16);
        hl[2*g+1] = lb[2] | (lb[3] << 16);
    }

    uint4* dst = (uint4*)(g_hb + (size_t)t * 128);
#pragma unroll
    for (int i = 0; i < 8; i++)
        dst[i] = make_uint4(hh[4*i], hh[4*i+1], hh[4*i+2], hh[4*i+3]);
#pragma unroll
    for (int i = 0; i < 8; i++)
        dst[8 + i] = make_uint4(hl[4*i], hl[4*i+1], hl[4*i+2], hl[4*i+3]);
}

// ---------------------------------------------------------------------------
// Kernel B (HMMA): out[t][e] = sum_k H[t][k]*W2[e][k] + b2[e]
// Three-term bf16 split: (Hh,Wh), (Hh,Wl), (Hl,Wh); terms 0/1 share A frags.
// CTA: 256 threads, tile 128 tokens x 128 e, 8 warps (4M x 2N), warp 32x64.
// Grid (4 e-blocks, 512 token-groups): consecutive CTAs share A tile in L2.
// ---------------------------------------------------------------------------
__global__ void __launch_bounds__(256, 2) gemm_hmma(
    const float* __restrict__ b2,
    float* __restrict__ out)
{
    extern __shared__ char dsm[];
    char* sA   = dsm;                              // [128][272B]: [Hh|Hl]
    char* sB   = dsm + SMEM_A_BYTES;               // [128][272B]: [Wh|Wl]
    float* b2s = (float*)(dsm + SMEM_A_BYTES + SMEM_B_BYTES);

    uint32_t sAu = smem_u32(sA);
    uint32_t sBu = smem_u32(sB);

    int tid = threadIdx.x;
    int e0  = blockIdx.x * NT;
    int gt0 = blockIdx.y * MT;

    // --- A tile: 128 rows x 256B, 2 threads per row, LDG.128 + STS ---
    {
        int row = tid >> 1, half = tid & 1;
        const uint4* src = (const uint4*)((const char*)g_hb
                          + (size_t)(gt0 + row) * 256 + half * 128);
        uint4* dst = (uint4*)(sA + row * ASTRIDE + half * 128);
        uint4 v[8];
#pragma unroll
        for (int j = 0; j < 8; j++) v[j] = src[j];
#pragma unroll
        for (int j = 0; j < 8; j++) dst[j] = v[j];
    }
    // --- B tile: 128 rows x 256B, 2 threads per row ---
    {
        int row = tid >> 1, half = tid & 1;
        const uint4* src = (const uint4*)((const char*)g_w2b
                          + (size_t)(e0 + row) * 256 + half * 128);
        uint4* dst = (uint4*)(sB + row * BSTRIDE + half * 128);
        uint4 v[8];
#pragma unroll
        for (int j = 0; j < 8; j++) v[j] = src[j];
#pragma unroll
        for (int j = 0; j < 8; j++) dst[j] = v[j];
    }
    if (tid < NT) b2s[tid] = b2[e0 + tid];
    __syncthreads();

    int wid = tid >> 5, l = tid & 31;
    int wm = wid & 3;        // M block (32 rows)
    int wn = wid >> 2;       // N block (64 cols)

    // Bias-initialized accumulators [mt][nt][4]
    float acc[2][8][4];
    {
        int cb = wn * 64 + (l & 3) * 2;
#pragma unroll
        for (int nt = 0; nt < 8; nt++) {
            float bv0 = b2s[cb + nt * 8];
            float bv1 = b2s[cb + nt * 8 + 1];
#pragma unroll
            for (int mt = 0; mt < 2; mt++) {
                acc[mt][nt][0] = bv0; acc[mt][nt][1] = bv1;
                acc[mt][nt][2] = bv0; acc[mt][nt][3] = bv1;
            }
        }
    }

    // ldmatrix per-lane bases
    uint32_t aBase = sAu + (uint32_t)(wm * 32 + (l & 15)) * ASTRIDE + ((l >> 4) << 4);
    uint32_t bRow  = (uint32_t)(wn * 64 + (l & 7) + ((l >> 4) << 3));
    uint32_t bBase = sBu + bRow * BSTRIDE + (((l >> 3) & 1) << 4);

    // ---- Stage 1: A = Hh shared across terms (Wh, Wl): 32 MMAs per kin ----
#pragma unroll
    for (int kin = 0; kin < 4; kin++) {
        uint32_t kb = (uint32_t)(kin * 32);

        uint32_t a[2][4];
#pragma unroll
        for (int mt = 0; mt < 2; mt++)
            LDSM_X4(a[mt][0], a[mt][1], a[mt][2], a[mt][3],
                    aBase + (uint32_t)(mt * 16) * ASTRIDE + kb);

        uint32_t bh[8][2], bl[8][2];
#pragma unroll
        for (int j = 0; j < 4; j++) {
            uint32_t r0, r1, r2, r3;
            LDSM_X4(r0, r1, r2, r3, bBase + (uint32_t)(j * 16) * BSTRIDE + kb);
            bh[2*j][0] = r0;  bh[2*j][1] = r1;
            bh[2*j+1][0] = r2; bh[2*j+1][1] = r3;
        }
#pragma unroll
        for (int j = 0; j < 4; j++) {
            uint32_t r0, r1, r2, r3;
            LDSM_X4(r0, r1, r2, r3, bBase + (uint32_t)(j * 16) * BSTRIDE + 128 + kb);
            bl[2*j][0] = r0;  bl[2*j][1] = r1;
            bl[2*j+1][0] = r2; bl[2*j+1][1] = r3;
        }

#pragma unroll
        for (int mt = 0; mt < 2; mt++)
#pragma unroll
            for (int nt = 0; nt < 8; nt++)
                MMA16816(acc[mt][nt], a[mt][0], a[mt][1], a[mt][2], a[mt][3],
                         bh[nt][0], bh[nt][1]);
#pragma unroll
        for (int mt = 0; mt < 2; mt++)
#pragma unroll
            for (int nt = 0; nt < 8; nt++)
                MMA16816(acc[mt][nt], a[mt][0], a[mt][1], a[mt][2], a[mt][3],
                         bl[nt][0], bl[nt][1]);
    }

    // ---- Stage 2: A = Hl (offset 128B), B = Wh: 16 MMAs per kin ----
#pragma unroll
    for (int kin = 0; kin < 4; kin++) {
        uint32_t kb = (uint32_t)(kin * 32);

        uint32_t a[2][4];
#pragma unroll
        for (int mt = 0; mt < 2; mt++)
            LDSM_X4(a[mt][0], a[mt][1], a[mt][2], a[mt][3],
                    aBase + (uint32_t)(mt * 16) * ASTRIDE + 128 + kb);

        uint32_t bh[8][2];
#pragma unroll
        for (int j = 0; j < 4; j++) {
            uint32_t r0, r1, r2, r3;
            LDSM_X4(r0, r1, r2, r3, bBase + (uint32_t)(j * 16) * BSTRIDE + kb);
            bh[2*j][0] = r0;  bh[2*j][1] = r1;
            bh[2*j+1][0] = r2; bh[2*j+1][1] = r3;
        }

#pragma unroll
        for (int mt = 0; mt < 2; mt++)
#pragma unroll
            for (int nt = 0; nt < 8; nt++)
                MMA16816(acc[mt][nt], a[mt][0], a[mt][1], a[mt][2], a[mt][3],
                         bh[nt][0], bh[nt][1]);
    }

    // Epilogue: direct coalesced float2 stores
    {
        int row_l = (l >> 2);
        int col_l = (l & 3) * 2;
#pragma unroll
        for (int mt = 0; mt < 2; mt++) {
            int r0 = gt0 + wm * 32 + mt * 16 + row_l;
            float* o0 = out + (size_t)r0 * EMBED + e0 + wn * 64 + col_l;
            float* o1 = out + (size_t)(r0 + 8) * EMBED + e0 + wn * 64 + col_l;
#pragma unroll
            for (int nt = 0; nt < 8; nt++) {
                *(float2*)(o0 + nt * 8) = make_float2(acc[mt][nt][0], acc[mt][nt][1]);
                *(float2*)(o1 + nt * 8) = make_float2(acc[mt][nt][2], acc[mt][nt][3]);
            }
        }
    }
}

// ---------------------------------------------------------------------------
extern "C" void kernel_launch(void* const* d_in, const int* in_sizes, int n_in,
                              void* d_out, int out_size)
{
    const float *x = nullptr, *theta = nullptr, *W1 = nullptr,
                *b1 = nullptr, *W2 = nullptr, *b2 = nullptr;
    for (int i = 0; i < n_in; i++) {
        switch (in_sizes[i]) {
            case NTOK * EMBED: x     = (const float*)d_in[i]; break;
            case NQ:           theta = (const float*)d_in[i]; break;
            case FFN * NQ:     W1    = (const float*)d_in[i]; break;
            case FFN:          b1    = (const float*)d_in[i]; break;
            case EMBED * FFN:  W2    = (const float*)d_in[i]; break;
            case EMBED:        b2    = (const float*)d_in[i]; break;
            default: break;
        }
    }
    float* out = (float*)d_out;

    static int smem_set = 0;
    if (!smem_set) {
        cudaFuncSetAttribute(gemm_hmma,
                             cudaFuncAttributeMaxDynamicSharedMemorySize,
                             SMEM_TOTAL);
        smem_set = 1;
    }

    h_kernel<<<NTOK / 128, 128>>>(x, theta, W1, b1, W2);
    gemm_hmma<<<dim3(EMBED / NT, NTOK / MT), 256, SMEM_TOTAL>>>(b2, out);
}

// round 11
// speedup vs baseline: 1.5041x; 1.1934x over previous
#include <cuda_runtime.h>
#include <cuda_bf16.h>
#include <cstdint>

// Problem dims
#define EMBED 512
#define FFN   64
#define NQ    16
#define NTOK  65536   // 16 * 4096

// GEMM tiling
#define MT 128              // tokens per CTA
#define NT 128              // embed outputs per CTA
#define ASTRIDE 272         // smem row stride bytes (256B data + 16B pad)
#define BSTRIDE 272
#define SMEM_A_BYTES (MT * ASTRIDE)          // 34816
#define SMEM_B_BYTES (NT * BSTRIDE)          // 34816
#define SMEM_TOTAL (SMEM_A_BYTES + SMEM_B_BYTES + 512)   // 70144

// H in bf16 split form: per token 128 bf16 = [Hh(64) | Hl(64)], 16 MiB
__device__ __align__(16) __nv_bfloat16 g_hb[(size_t)NTOK * 128];
// W2 in bf16 split form, sigma-permuted rows: per slot 128 bf16 = [Wh|Wl]
__device__ __align__(16) __nv_bfloat16 g_w2b[(size_t)EMBED * 128];

// sigma: within a 64-col group, slot s holds W2 row with low-6 bits permuted
// [b5 b4 | b3 | b2 b1 | b0] -> [b5 b4 | b2 b1 | b3 | b0]
__device__ __host__ __forceinline__ int sigma_phys(int L) {
    return 16 * (L >> 4) + 4 * ((L & 7) >> 1) + 2 * ((L >> 3) & 1) + (L & 1);
}

__device__ __forceinline__ uint32_t smem_u32(const void* p) {
    uint32_t a;
    asm("{ .reg .u64 t; cvta.to.shared.u64 t, %1; cvt.u32.u64 %0, t; }"
        : "=r"(a) : "l"(p));
    return a;
}

#define LDSM_X4(r0, r1, r2, r3, addr) \
    asm volatile("ldmatrix.sync.aligned.m8n8.x4.shared.b16 {%0,%1,%2,%3}, [%4];" \
                 : "=r"(r0), "=r"(r1), "=r"(r2), "=r"(r3) : "r"(addr))

#define MMA16816(d, a0, a1, a2, a3, b0, b1) \
    asm volatile("mma.sync.aligned.m16n8k16.row.col.f32.bf16.bf16.f32 " \
                 "{%0,%1,%2,%3}, {%4,%5,%6,%7}, {%8,%9}, {%0,%1,%2,%3};" \
                 : "+f"((d)[0]), "+f"((d)[1]), "+f"((d)[2]), "+f"((d)[3]) \
                 : "r"(a0), "r"(a1), "r"(a2), "r"(a3), "r"(b0), "r"(b1))

// ---------------------------------------------------------------------------
// Kernel A: H[t][f] = relu( sum_q cos(x[t][q])*cos(theta[q]) * W1[f][q] + b1[f] )
// R5-proven shape: 1 thread/token, 256-thr blocks, 2-chain inner, __cosf.
// Block 0 also builds sigma-permuted bf16-split W2 (2 slots per thread).
// ---------------------------------------------------------------------------
__global__ void __launch_bounds__(256) h_kernel(
    const float* __restrict__ x,
    const float* __restrict__ theta,
    const float* __restrict__ W1,
    const float* __restrict__ b1,
    const float* __restrict__ W2)
{
    __shared__ float ct[NQ];
    __shared__ float w1s[FFN * NQ];
    __shared__ float b1s[FFN];

    int tid = threadIdx.x;
    if (tid < NQ) ct[tid] = cosf(theta[tid]);   // 16 precise calls
    for (int i = tid; i < FFN * NQ; i += 256) w1s[i] = W1[i];
    if (tid < FFN) b1s[tid] = b1[tid];
    __syncthreads();

    // Block 0 side-job: sigma-permuted split of W2 (512 slots, 2 per thread)
    if (blockIdx.x == 0) {
#pragma unroll
        for (int rr = 0; rr < 2; rr++) {
            int s = tid + rr * 256;
            int e = (s & ~63) | sigma_phys(s & 63);
            const float4* src = (const float4*)(W2 + (size_t)e * FFN);
            uint32_t hh[32], ll[32];
#pragma unroll
            for (int i = 0; i < 16; i++) {
                float4 v = src[i];
                float f[4] = {v.x, v.y, v.z, v.w};
                uint32_t hb[4], lb[4];
#pragma unroll
                for (int c = 0; c < 4; c++) {
                    __nv_bfloat16 h = __float2bfloat16(f[c]);
                    __nv_bfloat16 l = __float2bfloat16(f[c] - __bfloat162float(h));
                    hb[c] = __bfloat16_as_ushort(h);
                    lb[c] = __bfloat16_as_ushort(l);
                }
                hh[2*i]   = hb[0] | (hb[1] << 16);
                hh[2*i+1] = hb[2] | (hb[3] << 16);
                ll[2*i]   = lb[0] | (lb[1] << 16);
                ll[2*i+1] = lb[2] | (lb[3] << 16);
            }
            uint4* dst = (uint4*)(g_w2b + (size_t)s * 128);
#pragma unroll
            for (int i = 0; i < 8; i++)
                dst[i] = make_uint4(hh[4*i], hh[4*i+1], hh[4*i+2], hh[4*i+3]);
#pragma unroll
            for (int i = 0; i < 8; i++)
                dst[8 + i] = make_uint4(ll[4*i], ll[4*i+1], ll[4*i+2], ll[4*i+3]);
        }
    }

    int t = blockIdx.x * 256 + tid;
    const float4* xr = (const float4*)(x + (size_t)t * EMBED);

    float z[NQ];
#pragma unroll
    for (int i = 0; i < 4; i++) {
        float4 v = xr[i];
        z[4*i + 0] = __cosf(v.x) * ct[4*i + 0];
        z[4*i + 1] = __cosf(v.y) * ct[4*i + 1];
        z[4*i + 2] = __cosf(v.z) * ct[4*i + 2];
        z[4*i + 3] = __cosf(v.w) * ct[4*i + 3];
    }

    uint32_t hh[32], hl[32];
#pragma unroll
    for (int p = 0; p < 32; p++) {
        int f0 = 2 * p;
        float a0 = b1s[f0], a1 = b1s[f0 + 1];
#pragma unroll
        for (int q = 0; q < NQ; q++) {
            a0 = fmaf(z[q], w1s[f0 * NQ + q], a0);
            a1 = fmaf(z[q], w1s[(f0 + 1) * NQ + q], a1);
        }
        a0 = fmaxf(a0, 0.0f);
        a1 = fmaxf(a1, 0.0f);
        __nv_bfloat16 h0 = __float2bfloat16(a0);
        __nv_bfloat16 h1 = __float2bfloat16(a1);
        __nv_bfloat16 l0 = __float2bfloat16(a0 - __bfloat162float(h0));
        __nv_bfloat16 l1 = __float2bfloat16(a1 - __bfloat162float(h1));
        hh[p] = (uint32_t)__bfloat16_as_ushort(h0) | ((uint32_t)__bfloat16_as_ushort(h1) << 16);
        hl[p] = (uint32_t)__bfloat16_as_ushort(l0) | ((uint32_t)__bfloat16_as_ushort(l1) << 16);
    }

    uint4* dst = (uint4*)(g_hb + (size_t)t * 128);
#pragma unroll
    for (int i = 0; i < 8; i++)
        dst[i] = make_uint4(hh[4*i], hh[4*i+1], hh[4*i+2], hh[4*i+3]);
#pragma unroll
    for (int i = 0; i < 8; i++)
        dst[8 + i] = make_uint4(hl[4*i], hl[4*i+1], hl[4*i+2], hl[4*i+3]);
}

// ---------------------------------------------------------------------------
// Kernel B (HMMA): out[t][e] = sum_k H[t][k]*W2[e][k] + b2[e]
// Three-term bf16 split: (Hh,Wh), (Hh,Wl), (Hl,Wh), staged per 16-k chunk so
// Ah and Bh fragments are reused; LDSM 48 x4/warp. sigma-permuted B columns
// give each thread 4 contiguous output floats -> STG.128 epilogue.
// CTA: 256 threads, tile 128x128, 8 warps (4M x 2N), warp 32x64. 2 CTAs/SM.
// Grid x = e-blocks (A tile shared in L2 by consecutive CTAs).
// ---------------------------------------------------------------------------
__global__ void __launch_bounds__(256, 2) gemm_hmma(
    const float* __restrict__ b2,
    float* __restrict__ out)
{
    extern __shared__ char dsm[];
    char* sA   = dsm;                              // [128][272B]: [Hh|Hl]
    char* sB   = dsm + SMEM_A_BYTES;               // [128][272B]: [Wh|Wl] (sigma)
    float* b2s = (float*)(dsm + SMEM_A_BYTES + SMEM_B_BYTES);

    uint32_t sAu = smem_u32(sA);
    uint32_t sBu = smem_u32(sB);

    int tid = threadIdx.x;
    int e0  = blockIdx.x * NT;
    int gt0 = blockIdx.y * MT;

    // --- A tile: 128 rows x 256B, 2 threads per row, LDG.128 + STS ---
    {
        int row = tid >> 1, half = tid & 1;
        const uint4* src = (const uint4*)((const char*)g_hb
                          + (size_t)(gt0 + row) * 256 + half * 128);
        uint4* dst = (uint4*)(sA + row * ASTRIDE + half * 128);
        uint4 v[8];
#pragma unroll
        for (int j = 0; j < 8; j++) v[j] = src[j];
#pragma unroll
        for (int j = 0; j < 8; j++) dst[j] = v[j];
    }
    // --- B tile: 128 slots x 256B, 2 threads per row (already sigma-ordered) ---
    {
        int row = tid >> 1, half = tid & 1;
        const uint4* src = (const uint4*)((const char*)g_w2b
                          + (size_t)(e0 + row) * 256 + half * 128);
        uint4* dst = (uint4*)(sB + row * BSTRIDE + half * 128);
        uint4 v[8];
#pragma unroll
        for (int j = 0; j < 8; j++) v[j] = src[j];
#pragma unroll
        for (int j = 0; j < 8; j++) dst[j] = v[j];
    }
    if (tid < NT) b2s[tid] = b2[e0 + tid];   // true e order
    __syncthreads();

    int wid = tid >> 5, l = tid & 31;
    int wm = wid & 3;        // M block (32 rows)
    int wn = wid >> 2;       // N block (64 cols)
    int c  = l & 3;          // quad within lane group

    // Bias-initialized accumulators [mt][nt][4]; col of acc[..][nt][j] is
    // wn*64 + 16*(nt>>1) + 4*c + 2*(nt&1) + j (true e space).
    float acc[2][8][4];
    {
        int cb = wn * 64;
#pragma unroll
        for (int nt = 0; nt < 8; nt++) {
            int col = cb + 16 * (nt >> 1) + 4 * c + 2 * (nt & 1);
            float bv0 = b2s[col];
            float bv1 = b2s[col + 1];
#pragma unroll
            for (int mt = 0; mt < 2; mt++) {
                acc[mt][nt][0] = bv0; acc[mt][nt][1] = bv1;
                acc[mt][nt][2] = bv0; acc[mt][nt][3] = bv1;
            }
        }
    }

    // ldmatrix per-lane bases
    uint32_t aBase = sAu + (uint32_t)(wm * 32 + (l & 15)) * ASTRIDE + ((l >> 4) << 4);
    uint32_t bRow  = (uint32_t)(wn * 64 + (l & 7) + ((l >> 4) << 3));
    uint32_t bBase = sBu + bRow * BSTRIDE + (((l >> 3) & 1) << 4);

    // ---- K loop: per 16-k chunk, stage (Ah*Bh), (Ah*Bl), (Al*Bh) ----
#pragma unroll
    for (int kin = 0; kin < 4; kin++) {
        uint32_t kb = (uint32_t)(kin * 32);

        uint32_t ah[2][4];
#pragma unroll
        for (int mt = 0; mt < 2; mt++)
            LDSM_X4(ah[mt][0], ah[mt][1], ah[mt][2], ah[mt][3],
                    aBase + (uint32_t)(mt * 16) * ASTRIDE + kb);

        uint32_t bh[8][2];
#pragma unroll
        for (int j = 0; j < 4; j++) {
            uint32_t r0, r1, r2, r3;
            LDSM_X4(r0, r1, r2, r3, bBase + (uint32_t)(j * 16) * BSTRIDE + kb);
            bh[2*j][0] = r0;  bh[2*j][1] = r1;
            bh[2*j+1][0] = r2; bh[2*j+1][1] = r3;
        }

        // term 0: Hh * Wh
#pragma unroll
        for (int mt = 0; mt < 2; mt++)
#pragma unroll
            for (int nt = 0; nt < 8; nt++)
                MMA16816(acc[mt][nt], ah[mt][0], ah[mt][1], ah[mt][2], ah[mt][3],
                         bh[nt][0], bh[nt][1]);

        uint32_t bl[8][2];
#pragma unroll
        for (int j = 0; j < 4; j++) {
            uint32_t r0, r1, r2, r3;
            LDSM_X4(r0, r1, r2, r3, bBase + (uint32_t)(j * 16) * BSTRIDE + 128 + kb);
            bl[2*j][0] = r0;  bl[2*j][1] = r1;
            bl[2*j+1][0] = r2; bl[2*j+1][1] = r3;
        }

        // term 1: Hh * Wl
#pragma unroll
        for (int mt = 0; mt < 2; mt++)
#pragma unroll
            for (int nt = 0; nt < 8; nt++)
                MMA16816(acc[mt][nt], ah[mt][0], ah[mt][1], ah[mt][2], ah[mt][3],
                         bl[nt][0], bl[nt][1]);

        uint32_t al[2][4];
#pragma unroll
        for (int mt = 0; mt < 2; mt++)
            LDSM_X4(al[mt][0], al[mt][1], al[mt][2], al[mt][3],
                    aBase + (uint32_t)(mt * 16) * ASTRIDE + 128 + kb);

        // term 2: Hl * Wh
#pragma unroll
        for (int mt = 0; mt < 2; mt++)
#pragma unroll
            for (int nt = 0; nt < 8; nt++)
                MMA16816(acc[mt][nt], al[mt][0], al[mt][1], al[mt][2], al[mt][3],
                         bh[nt][0], bh[nt][1]);
    }

    // Epilogue: sigma layout -> each thread owns contiguous float4 runs.
    // Instr g covers cols wn*64 + 16g + 4c + [0,4).
    {
        int row_l = l >> 2;
#pragma unroll
        for (int mt = 0; mt < 2; mt++) {
            int r0 = gt0 + wm * 32 + mt * 16 + row_l;
            float* base0 = out + (size_t)r0 * EMBED + e0 + wn * 64;
            float* base1 = base0 + (size_t)8 * EMBED;
#pragma unroll
            for (int g = 0; g < 4; g++) {
                float4 v0, v1;
                v0.x = acc[mt][2*g][0];   v0.y = acc[mt][2*g][1];
                v0.z = acc[mt][2*g+1][0]; v0.w = acc[mt][2*g+1][1];
                v1.x = acc[mt][2*g][2];   v1.y = acc[mt][2*g][3];
                v1.z = acc[mt][2*g+1][2]; v1.w = acc[mt][2*g+1][3];
                *(float4*)(base0 + 16 * g + 4 * c) = v0;
                *(float4*)(base1 + 16 * g + 4 * c) = v1;
            }
        }
    }
}

// ---------------------------------------------------------------------------
extern "C" void kernel_launch(void* const* d_in, const int* in_sizes, int n_in,
                              void* d_out, int out_size)
{
    const float *x = nullptr, *theta = nullptr, *W1 = nullptr,
                *b1 = nullptr, *W2 = nullptr, *b2 = nullptr;
    for (int i = 0; i < n_in; i++) {
        switch (in_sizes[i]) {
            case NTOK * EMBED: x     = (const float*)d_in[i]; break;
            case NQ:           theta = (const float*)d_in[i]; break;
            case FFN * NQ:     W1    = (const float*)d_in[i]; break;
            case FFN:          b1    = (const float*)d_in[i]; break;
            case EMBED * FFN:  W2    = (const float*)d_in[i]; break;
            case EMBED:        b2    = (const float*)d_in[i]; break;
            default: break;
        }
    }
    float* out = (float*)d_out;

    static int smem_set = 0;
    if (!smem_set) {
        cudaFuncSetAttribute(gemm_hmma,
                             cudaFuncAttributeMaxDynamicSharedMemorySize,
                             SMEM_TOTAL);
        smem_set = 1;
    }

    h_kernel<<<NTOK / 256, 256>>>(x, theta, W1, b1, W2);
    gemm_hmma<<<dim3(EMBED / NT, NTOK / MT), 256, SMEM_TOTAL>>>(b2, out);
}

// round 12
// speedup vs baseline: 1.9991x; 1.3290x over previous
#include <cuda_runtime.h>
#include <cuda_bf16.h>
#include <cstdint>

// Problem dims
#define EMBED 512
#define FFN   64
#define NQ    16
#define NTOK  65536   // 16 * 4096

// GEMM tiling
#define MT 128              // tokens per CTA
#define NT 128              // embed outputs per CTA
#define ASTRIDE 272         // A/B smem row stride bytes (256B data + 16B pad)
#define BSTRIDE 272
#define ZSTRIDE 80          // z tile row stride (64B data + 16B pad)
#define W1STRIDE 80

// smem offsets
#define OFF_A   0
#define OFF_B   34816
#define OFF_Z   69632                 // 128 * 80 = 10240
#define OFF_W1  79872                 // 64 * 80  = 5120
#define OFF_B1  84992                 // 64 floats = 256
#define OFF_B2  85248                 // 128 floats = 512
#define OFF_CT  85760                 // 16 floats = 64
#define SMEM_TOTAL 85824

// sigma: within a 64-col group, slot s holds W2 row with low-6 bits permuted
// [b5 b4 | b3 | b2 b1 | b0] -> [b5 b4 | b2 b1 | b3 | b0]
__device__ __forceinline__ int sigma_phys(int L) {
    return 16 * (L >> 4) + 4 * ((L & 7) >> 1) + 2 * ((L >> 3) & 1) + (L & 1);
}

__device__ __forceinline__ uint32_t smem_u32(const void* p) {
    uint32_t a;
    asm("{ .reg .u64 t; cvta.to.shared.u64 t, %1; cvt.u32.u64 %0, t; }"
        : "=r"(a) : "l"(p));
    return a;
}

#define LDSM_X4(r0, r1, r2, r3, addr) \
    asm volatile("ldmatrix.sync.aligned.m8n8.x4.shared.b16 {%0,%1,%2,%3}, [%4];" \
                 : "=r"(r0), "=r"(r1), "=r"(r2), "=r"(r3) : "r"(addr))

#define MMA16816(d, a0, a1, a2, a3, b0, b1) \
    asm volatile("mma.sync.aligned.m16n8k16.row.col.f32.bf16.bf16.f32 " \
                 "{%0,%1,%2,%3}, {%4,%5,%6,%7}, {%8,%9}, {%0,%1,%2,%3};" \
                 : "+f"((d)[0]), "+f"((d)[1]), "+f"((d)[2]), "+f"((d)[3]) \
                 : "r"(a0), "r"(a1), "r"(a2), "r"(a3), "r"(b0), "r"(b1))

__device__ __forceinline__ void bf16_split2(float v0, float v1,
                                            uint32_t& hi, uint32_t& lo) {
    __nv_bfloat16 h0 = __float2bfloat16(v0);
    __nv_bfloat16 h1 = __float2bfloat16(v1);
    __nv_bfloat16 l0 = __float2bfloat16(v0 - __bfloat162float(h0));
    __nv_bfloat16 l1 = __float2bfloat16(v1 - __bfloat162float(h1));
    hi = (uint32_t)__bfloat16_as_ushort(h0) | ((uint32_t)__bfloat16_as_ushort(h1) << 16);
    lo = (uint32_t)__bfloat16_as_ushort(l0) | ((uint32_t)__bfloat16_as_ushort(l1) << 16);
}

// ---------------------------------------------------------------------------
// Fully fused kernel. Per CTA (128 tokens x 128 e):
//  Phase 0: LDG x-slice, W1, W2 tile, biases, theta-cos.
//  Phase 1: z = cos(x)*cos(theta) bf16-split -> sZ; W1 split -> sW1;
//           W2 split (sigma-permuted) -> sB.
//  Phase 2: H = relu(z @ W1^T + b1) via 3-term bf16 MMA; fragments split
//           straight into sA ([Hh|Hl] layout).
//  Phase 3: main 3-term GEMM (R11 code) + sigma STG.128 epilogue.
// ---------------------------------------------------------------------------
__global__ void __launch_bounds__(256, 2) fused_ffn(
    const float* __restrict__ x,
    const float* __restrict__ theta,
    const float* __restrict__ W1,
    const float* __restrict__ b1,
    const float* __restrict__ W2,
    const float* __restrict__ b2,
    float* __restrict__ out)
{
    extern __shared__ char dsm[];
    char*  sA  = dsm + OFF_A;
    char*  sB  = dsm + OFF_B;
    char*  sZ  = dsm + OFF_Z;
    char*  sW1 = dsm + OFF_W1;
    float* b1s = (float*)(dsm + OFF_B1);
    float* b2s = (float*)(dsm + OFF_B2);
    float* cts = (float*)(dsm + OFF_CT);

    uint32_t sAu  = smem_u32(sA);
    uint32_t sBu  = smem_u32(sB);
    uint32_t sZu  = smem_u32(sZ);
    uint32_t sW1u = smem_u32(sW1);

    int tid = threadIdx.x;
    int e0  = blockIdx.x * NT;
    int gt0 = blockIdx.y * MT;

    // ---------------- Phase 0: global loads into registers ----------------
    int zrow = tid >> 1, zhalf = tid & 1;            // 2 threads per token
    const float4* xp = (const float4*)(x + (size_t)(gt0 + zrow) * EMBED + zhalf * 8);
    float4 xv0 = xp[0], xv1 = xp[1];

    int w1row = tid >> 2, w1q = tid & 3;             // 4 threads per W1 row
    float4 w1v = *(const float4*)(W1 + (size_t)w1row * NQ + w1q * 4);

    int bslot = tid >> 1, bhalf = tid & 1;           // 2 threads per B slot
    int erow  = e0 + ((bslot & ~63) | sigma_phys(bslot & 63));
    float4 w2v[8];
    {
        const float4* wp = (const float4*)(W2 + (size_t)erow * FFN + bhalf * 32);
#pragma unroll
        for (int i = 0; i < 8; i++) w2v[i] = wp[i];
    }

    if (tid < NQ)  cts[tid] = cosf(theta[tid]);
    if (tid < FFN) b1s[tid] = b1[tid];
    if (tid < NT)  b2s[tid] = b2[e0 + tid];
    __syncthreads();                                  // cts visible

    // ---------------- Phase 1: splits into smem ----------------
    // z tile row: [zh k0-7 |16B| zh k8-15 |16B| zl k0-7 | zl k8-15]
    {
        float zf[8];
        float xf[8] = {xv0.x, xv0.y, xv0.z, xv0.w, xv1.x, xv1.y, xv1.z, xv1.w};
#pragma unroll
        for (int j = 0; j < 8; j++)
            zf[j] = __cosf(xf[j]) * cts[zhalf * 8 + j];
        uint32_t hi[4], lo[4];
#pragma unroll
        for (int j = 0; j < 4; j++)
            bf16_split2(zf[2*j], zf[2*j+1], hi[j], lo[j]);
        *(uint4*)(sZ + zrow * ZSTRIDE + zhalf * 16)      = make_uint4(hi[0], hi[1], hi[2], hi[3]);
        *(uint4*)(sZ + zrow * ZSTRIDE + 32 + zhalf * 16) = make_uint4(lo[0], lo[1], lo[2], lo[3]);
    }
    // W1 tile row: [w1h 16 bf16 (32B) | w1l (32B)]
    {
        uint32_t h0, l0, h1, l1;
        bf16_split2(w1v.x, w1v.y, h0, l0);
        bf16_split2(w1v.z, w1v.w, h1, l1);
        *(uint2*)(sW1 + w1row * W1STRIDE + w1q * 8)      = make_uint2(h0, h1);
        *(uint2*)(sW1 + w1row * W1STRIDE + 32 + w1q * 8) = make_uint2(l0, l1);
    }
    // W2 tile slot: [Wh 64 bf16 (128B) | Wl (128B)], sigma row order
    {
        uint32_t hi[16], lo[16];
#pragma unroll
        for (int i = 0; i < 8; i++) {
            bf16_split2(w2v[i].x, w2v[i].y, hi[2*i],   lo[2*i]);
            bf16_split2(w2v[i].z, w2v[i].w, hi[2*i+1], lo[2*i+1]);
        }
        char* rb = sB + bslot * BSTRIDE + bhalf * 64;
        *(uint4*)(rb)            = make_uint4(hi[0], hi[1], hi[2], hi[3]);
        *(uint4*)(rb + 16)       = make_uint4(hi[4], hi[5], hi[6], hi[7]);
        *(uint4*)(rb + 32)       = make_uint4(hi[8], hi[9], hi[10], hi[11]);
        *(uint4*)(rb + 48)       = make_uint4(hi[12], hi[13], hi[14], hi[15]);
        *(uint4*)(rb + 128)      = make_uint4(lo[0], lo[1], lo[2], lo[3]);
        *(uint4*)(rb + 128 + 16) = make_uint4(lo[4], lo[5], lo[6], lo[7]);
        *(uint4*)(rb + 128 + 32) = make_uint4(lo[8], lo[9], lo[10], lo[11]);
        *(uint4*)(rb + 128 + 48) = make_uint4(lo[12], lo[13], lo[14], lo[15]);
    }
    __syncthreads();

    int wid = tid >> 5, l = tid & 31;
    int wm = wid & 3;        // M block (32 token rows)
    int wn = wid >> 2;       // N block (64 e cols / 32 FFN cols in H phase)
    int c  = l & 3;

    // ---------------- Phase 2: H MMA (128 x 64 x 16, 3 terms) ----------------
    {
        uint32_t zBase  = sZu  + (uint32_t)(wm * 32 + (l & 15)) * ZSTRIDE + ((l >> 4) << 4);
        uint32_t w1Base = sW1u + (uint32_t)(wn * 32 + (l & 7) + ((l >> 4) << 3)) * W1STRIDE
                               + (((l >> 3) & 1) << 4);

        float hacc[2][4][4];
#pragma unroll
        for (int nt = 0; nt < 4; nt++) {
            int C = wn * 32 + nt * 8 + c * 2;
            float bv0 = b1s[C], bv1 = b1s[C + 1];
#pragma unroll
            for (int mt = 0; mt < 2; mt++) {
                hacc[mt][nt][0] = bv0; hacc[mt][nt][1] = bv1;
                hacc[mt][nt][2] = bv0; hacc[mt][nt][3] = bv1;
            }
        }

        uint32_t zh[2][4], zl[2][4];
#pragma unroll
        for (int mt = 0; mt < 2; mt++) {
            LDSM_X4(zh[mt][0], zh[mt][1], zh[mt][2], zh[mt][3],
                    zBase + (uint32_t)(mt * 16) * ZSTRIDE);
            LDSM_X4(zl[mt][0], zl[mt][1], zl[mt][2], zl[mt][3],
                    zBase + (uint32_t)(mt * 16) * ZSTRIDE + 32);
        }
        uint32_t wh[4][2], wl[4][2];
#pragma unroll
        for (int j = 0; j < 2; j++) {
            uint32_t r0, r1, r2, r3;
            LDSM_X4(r0, r1, r2, r3, w1Base + (uint32_t)(j * 16) * W1STRIDE);
            wh[2*j][0] = r0;  wh[2*j][1] = r1;
            wh[2*j+1][0] = r2; wh[2*j+1][1] = r3;
            LDSM_X4(r0, r1, r2, r3, w1Base + (uint32_t)(j * 16) * W1STRIDE + 32);
            wl[2*j][0] = r0;  wl[2*j][1] = r1;
            wl[2*j+1][0] = r2; wl[2*j+1][1] = r3;
        }

#pragma unroll
        for (int mt = 0; mt < 2; mt++)
#pragma unroll
            for (int nt = 0; nt < 4; nt++) {
                MMA16816(hacc[mt][nt], zh[mt][0], zh[mt][1], zh[mt][2], zh[mt][3],
                         wh[nt][0], wh[nt][1]);
                MMA16816(hacc[mt][nt], zh[mt][0], zh[mt][1], zh[mt][2], zh[mt][3],
                         wl[nt][0], wl[nt][1]);
                MMA16816(hacc[mt][nt], zl[mt][0], zl[mt][1], zl[mt][2], zl[mt][3],
                         wh[nt][0], wh[nt][1]);
            }

        // relu + split -> sA fragments: row R cols [C,C+1]; [Hh | Hl @ +128B]
#pragma unroll
        for (int mt = 0; mt < 2; mt++)
#pragma unroll
            for (int nt = 0; nt < 4; nt++) {
                int C = wn * 32 + nt * 8 + c * 2;
                int R = wm * 32 + mt * 16 + (l >> 2);
                float v0 = fmaxf(hacc[mt][nt][0], 0.0f);
                float v1 = fmaxf(hacc[mt][nt][1], 0.0f);
                float v2 = fmaxf(hacc[mt][nt][2], 0.0f);
                float v3 = fmaxf(hacc[mt][nt][3], 0.0f);
                uint32_t hi01, lo01, hi23, lo23;
                bf16_split2(v0, v1, hi01, lo01);
                bf16_split2(v2, v3, hi23, lo23);
                *(uint32_t*)(sA + R * ASTRIDE + C * 2)             = hi01;
                *(uint32_t*)(sA + R * ASTRIDE + 128 + C * 2)       = lo01;
                *(uint32_t*)(sA + (R + 8) * ASTRIDE + C * 2)       = hi23;
                *(uint32_t*)(sA + (R + 8) * ASTRIDE + 128 + C * 2) = lo23;
            }
    }
    __syncthreads();

    // ---------------- Phase 3: main GEMM (R11-proven) ----------------
    float acc[2][8][4];
    {
        int cb = wn * 64;
#pragma unroll
        for (int nt = 0; nt < 8; nt++) {
            int col = cb + 16 * (nt >> 1) + 4 * c + 2 * (nt & 1);
            float bv0 = b2s[col];
            float bv1 = b2s[col + 1];
#pragma unroll
            for (int mt = 0; mt < 2; mt++) {
                acc[mt][nt][0] = bv0; acc[mt][nt][1] = bv1;
                acc[mt][nt][2] = bv0; acc[mt][nt][3] = bv1;
            }
        }
    }

    uint32_t aBase = sAu + (uint32_t)(wm * 32 + (l & 15)) * ASTRIDE + ((l >> 4) << 4);
    uint32_t bRow  = (uint32_t)(wn * 64 + (l & 7) + ((l >> 4) << 3));
    uint32_t bBase = sBu + bRow * BSTRIDE + (((l >> 3) & 1) << 4);

#pragma unroll
    for (int kin = 0; kin < 4; kin++) {
        uint32_t kb = (uint32_t)(kin * 32);

        uint32_t ah[2][4];
#pragma unroll
        for (int mt = 0; mt < 2; mt++)
            LDSM_X4(ah[mt][0], ah[mt][1], ah[mt][2], ah[mt][3],
                    aBase + (uint32_t)(mt * 16) * ASTRIDE + kb);

        uint32_t bh[8][2];
#pragma unroll
        for (int j = 0; j < 4; j++) {
            uint32_t r0, r1, r2, r3;
            LDSM_X4(r0, r1, r2, r3, bBase + (uint32_t)(j * 16) * BSTRIDE + kb);
            bh[2*j][0] = r0;  bh[2*j][1] = r1;
            bh[2*j+1][0] = r2; bh[2*j+1][1] = r3;
        }

#pragma unroll
        for (int mt = 0; mt < 2; mt++)
#pragma unroll
            for (int nt = 0; nt < 8; nt++)
                MMA16816(acc[mt][nt], ah[mt][0], ah[mt][1], ah[mt][2], ah[mt][3],
                         bh[nt][0], bh[nt][1]);

        uint32_t bl[8][2];
#pragma unroll
        for (int j = 0; j < 4; j++) {
            uint32_t r0, r1, r2, r3;
            LDSM_X4(r0, r1, r2, r3, bBase + (uint32_t)(j * 16) * BSTRIDE + 128 + kb);
            bl[2*j][0] = r0;  bl[2*j][1] = r1;
            bl[2*j+1][0] = r2; bl[2*j+1][1] = r3;
        }

#pragma unroll
        for (int mt = 0; mt < 2; mt++)
#pragma unroll
            for (int nt = 0; nt < 8; nt++)
                MMA16816(acc[mt][nt], ah[mt][0], ah[mt][1], ah[mt][2], ah[mt][3],
                         bl[nt][0], bl[nt][1]);

        uint32_t al[2][4];
#pragma unroll
        for (int mt = 0; mt < 2; mt++)
            LDSM_X4(al[mt][0], al[mt][1], al[mt][2], al[mt][3],
                    aBase + (uint32_t)(mt * 16) * ASTRIDE + 128 + kb);

#pragma unroll
        for (int mt = 0; mt < 2; mt++)
#pragma unroll
            for (int nt = 0; nt < 8; nt++)
                MMA16816(acc[mt][nt], al[mt][0], al[mt][1], al[mt][2], al[mt][3],
                         bh[nt][0], bh[nt][1]);
    }

    // Epilogue: sigma layout -> contiguous float4 per thread
    {
        int row_l = l >> 2;
#pragma unroll
        for (int mt = 0; mt < 2; mt++) {
            int r0 = gt0 + wm * 32 + mt * 16 + row_l;
            float* base0 = out + (size_t)r0 * EMBED + e0 + wn * 64;
            float* base1 = base0 + (size_t)8 * EMBED;
#pragma unroll
            for (int g = 0; g < 4; g++) {
                float4 v0, v1;
                v0.x = acc[mt][2*g][0];   v0.y = acc[mt][2*g][1];
                v0.z = acc[mt][2*g+1][0]; v0.w = acc[mt][2*g+1][1];
                v1.x = acc[mt][2*g][2];   v1.y = acc[mt][2*g][3];
                v1.z = acc[mt][2*g+1][2]; v1.w = acc[mt][2*g+1][3];
                *(float4*)(base0 + 16 * g + 4 * c) = v0;
                *(float4*)(base1 + 16 * g + 4 * c) = v1;
            }
        }
    }
}

// ---------------------------------------------------------------------------
extern "C" void kernel_launch(void* const* d_in, const int* in_sizes, int n_in,
                              void* d_out, int out_size)
{
    const float *x = nullptr, *theta = nullptr, *W1 = nullptr,
                *b1 = nullptr, *W2 = nullptr, *b2 = nullptr;
    for (int i = 0; i < n_in; i++) {
        switch (in_sizes[i]) {
            case NTOK * EMBED: x     = (const float*)d_in[i]; break;
            case NQ:           theta = (const float*)d_in[i]; break;
            case FFN * NQ:     W1    = (const float*)d_in[i]; break;
            case FFN:          b1    = (const float*)d_in[i]; break;
            case EMBED * FFN:  W2    = (const float*)d_in[i]; break;
            case EMBED:        b2    = (const float*)d_in[i]; break;
            default: break;
        }
    }
    float* out = (float*)d_out;

    static int smem_set = 0;
    if (!smem_set) {
        cudaFuncSetAttribute(fused_ffn,
                             cudaFuncAttributeMaxDynamicSharedMemorySize,
                             SMEM_TOTAL);
        smem_set = 1;
    }

    fused_ffn<<<dim3(EMBED / NT, NTOK / MT), 256, SMEM_TOTAL>>>(
        x, theta, W1, b1, W2, b2, out);
}

// round 13
// speedup vs baseline: 2.0480x; 1.0244x over previous
#include <cuda_runtime.h>
#include <cuda_bf16.h>
#include <cstdint>

// Problem dims
#define EMBED 512
#define FFN   64
#define NQ    16
#define NTOK  65536   // 16 * 4096

// GEMM tiling
#define MT 128              // tokens per CTA
#define NT 128              // embed outputs per CTA
#define ASTRIDE 272         // A/B smem row stride bytes (256B data + 16B pad)
#define BSTRIDE 272
#define ZSTRIDE 80          // z tile row stride (64B data + 16B pad)
#define W1STRIDE 80

// smem offsets
#define OFF_A   0
#define OFF_B   34816
#define OFF_Z   69632                 // 128 * 80 = 10240
#define OFF_W1  79872                 // 64 * 80  = 5120
#define OFF_B1  84992                 // 64 floats = 256
#define OFF_B2  85248                 // 128 floats = 512
#define SMEM_TOTAL 85760

// sigma: within a 64-col group, slot s holds W2 row sigma(s):
// s=(b5 b4 b3 b2 b1 b0) -> phys=(b5 b4 b2 b1 b3 b0)
__device__ __forceinline__ int sigma_inv(int p) {
    // inverse: (p5 p4 p3 p2 p1 p0) -> (p5 p4 p1 p3 p2 p0)
    return 16 * (p >> 4) + 8 * ((p >> 1) & 1) + 2 * ((p >> 2) & 3) + (p & 1);
}

__device__ __forceinline__ uint32_t smem_u32(const void* p) {
    uint32_t a;
    asm("{ .reg .u64 t; cvta.to.shared.u64 t, %1; cvt.u32.u64 %0, t; }"
        : "=r"(a) : "l"(p));
    return a;
}

#define LDSM_X4(r0, r1, r2, r3, addr) \
    asm volatile("ldmatrix.sync.aligned.m8n8.x4.shared.b16 {%0,%1,%2,%3}, [%4];" \
                 : "=r"(r0), "=r"(r1), "=r"(r2), "=r"(r3) : "r"(addr))

#define MMA16816(d, a0, a1, a2, a3, b0, b1) \
    asm volatile("mma.sync.aligned.m16n8k16.row.col.f32.bf16.bf16.f32 " \
                 "{%0,%1,%2,%3}, {%4,%5,%6,%7}, {%8,%9}, {%0,%1,%2,%3};" \
                 : "+f"((d)[0]), "+f"((d)[1]), "+f"((d)[2]), "+f"((d)[3]) \
                 : "r"(a0), "r"(a1), "r"(a2), "r"(a3), "r"(b0), "r"(b1))

// Exact truncation split: v = hi + lo, hi = bf16-trunc(v), lo exactly bf16.
// Packs two values with PRMT (result = {v0_hi16, v1_hi16}).
__device__ __forceinline__ void trunc_split2(float v0, float v1,
                                             uint32_t& hi, uint32_t& lo) {
    uint32_t u0 = __float_as_uint(v0), u1 = __float_as_uint(v1);
    float h0 = __uint_as_float(u0 & 0xFFFF0000u);
    float h1 = __uint_as_float(u1 & 0xFFFF0000u);
    float l0 = v0 - h0, l1 = v1 - h1;       // exact (Dekker truncation)
    asm("prmt.b32 %0, %1, %2, 0x7632;" : "=r"(hi) : "r"(u0), "r"(u1));
    asm("prmt.b32 %0, %1, %2, 0x7632;" : "=r"(lo)
        : "r"(__float_as_uint(l0)), "r"(__float_as_uint(l1)));
}

// ---------------------------------------------------------------------------
// Fully fused kernel. Per CTA (128 tokens x 128 e):
//  Phase 0/1: LDG x-slice, W1, W2 (coalesced, sigma^-1 STS), biases;
//             trunc-split z, W1, W2 into smem.
//  Phase 2: H = relu(z @ W1^T + b1) via 3-term bf16 MMA -> split into sA.
//  Phase 3: main 3-term GEMM + sigma STG.128 epilogue.
// ---------------------------------------------------------------------------
__global__ void __launch_bounds__(256, 2) fused_ffn(
    const float* __restrict__ x,
    const float* __restrict__ theta,
    const float* __restrict__ W1,
    const float* __restrict__ b1,
    const float* __restrict__ W2,
    const float* __restrict__ b2,
    float* __restrict__ out)
{
    extern __shared__ char dsm[];
    char*  sA  = dsm + OFF_A;
    char*  sB  = dsm + OFF_B;
    char*  sZ  = dsm + OFF_Z;
    char*  sW1 = dsm + OFF_W1;
    float* b1s = (float*)(dsm + OFF_B1);
    float* b2s = (float*)(dsm + OFF_B2);

    uint32_t sAu  = smem_u32(sA);
    uint32_t sBu  = smem_u32(sB);
    uint32_t sZu  = smem_u32(sZ);
    uint32_t sW1u = smem_u32(sW1);

    int tid = threadIdx.x;
    int e0  = blockIdx.x * NT;
    int gt0 = blockIdx.y * MT;

    // ---------------- Phase 0: global loads ----------------
    int zrow = tid >> 1, zhalf = tid & 1;            // 2 threads per token
    const float4* xp = (const float4*)(x + (size_t)(gt0 + zrow) * EMBED + zhalf * 8);
    float4 xv0 = xp[0], xv1 = xp[1];

    int w1row = tid >> 2, w1q = tid & 3;             // 4 threads per W1 row
    float4 w1v = *(const float4*)(W1 + (size_t)w1row * NQ + w1q * 4);

    int wrow = tid >> 1, whalf = tid & 1;            // linear (coalesced) W2 rows
    float4 w2v[8];
    {
        const float4* wp = (const float4*)(W2 + (size_t)(e0 + wrow) * FFN + whalf * 32);
#pragma unroll
        for (int i = 0; i < 8; i++) w2v[i] = wp[i];
    }

    if (tid < FFN) b1s[tid] = b1[tid];
    if (tid < NT)  b2s[tid] = b2[e0 + tid];

    // ---------------- Phase 1: splits into smem ----------------
    // z tile row: [zh k0-7 | zh k8-15 | zl k0-7 | zl k8-15]
    {
        float zf[8];
        float xf[8] = {xv0.x, xv0.y, xv0.z, xv0.w, xv1.x, xv1.y, xv1.z, xv1.w};
#pragma unroll
        for (int j = 0; j < 8; j++)
            zf[j] = __cosf(xf[j]) * __cosf(theta[zhalf * 8 + j]);
        uint32_t hi[4], lo[4];
#pragma unroll
        for (int j = 0; j < 4; j++)
            trunc_split2(zf[2*j], zf[2*j+1], hi[j], lo[j]);
        *(uint4*)(sZ + zrow * ZSTRIDE + zhalf * 16)      = make_uint4(hi[0], hi[1], hi[2], hi[3]);
        *(uint4*)(sZ + zrow * ZSTRIDE + 32 + zhalf * 16) = make_uint4(lo[0], lo[1], lo[2], lo[3]);
    }
    // W1 tile row: [w1h 16 bf16 (32B) | w1l (32B)]
    {
        uint32_t h0, l0, h1, l1;
        trunc_split2(w1v.x, w1v.y, h0, l0);
        trunc_split2(w1v.z, w1v.w, h1, l1);
        *(uint2*)(sW1 + w1row * W1STRIDE + w1q * 8)      = make_uint2(h0, h1);
        *(uint2*)(sW1 + w1row * W1STRIDE + 32 + w1q * 8) = make_uint2(l0, l1);
    }
    // W2 tile: slot s holds row sigma(s); we loaded row wrow -> slot sigma_inv
    {
        uint32_t hi[16], lo[16];
#pragma unroll
        for (int i = 0; i < 8; i++) {
            trunc_split2(w2v[i].x, w2v[i].y, hi[2*i],   lo[2*i]);
            trunc_split2(w2v[i].z, w2v[i].w, hi[2*i+1], lo[2*i+1]);
        }
        int slot = (wrow & ~63) | sigma_inv(wrow & 63);
        char* rb = sB + slot * BSTRIDE + whalf * 64;
        *(uint4*)(rb)            = make_uint4(hi[0], hi[1], hi[2], hi[3]);
        *(uint4*)(rb + 16)       = make_uint4(hi[4], hi[5], hi[6], hi[7]);
        *(uint4*)(rb + 32)       = make_uint4(hi[8], hi[9], hi[10], hi[11]);
        *(uint4*)(rb + 48)       = make_uint4(hi[12], hi[13], hi[14], hi[15]);
        *(uint4*)(rb + 128)      = make_uint4(lo[0], lo[1], lo[2], lo[3]);
        *(uint4*)(rb + 128 + 16) = make_uint4(lo[4], lo[5], lo[6], lo[7]);
        *(uint4*)(rb + 128 + 32) = make_uint4(lo[8], lo[9], lo[10], lo[11]);
        *(uint4*)(rb + 128 + 48) = make_uint4(lo[12], lo[13], lo[14], lo[15]);
    }
    __syncthreads();

    int wid = tid >> 5, l = tid & 31;
    int wm = wid & 3;        // M block (32 token rows)
    int wn = wid >> 2;       // N block
    int c  = l & 3;

    // ---------------- Phase 2: H MMA (128 x 64 x 16, 3 terms) ----------------
    {
        uint32_t zBase  = sZu  + (uint32_t)(wm * 32 + (l & 15)) * ZSTRIDE + ((l >> 4) << 4);
        uint32_t w1Base = sW1u + (uint32_t)(wn * 32 + (l & 7) + ((l >> 4) << 3)) * W1STRIDE
                               + (((l >> 3) & 1) << 4);

        float hacc[2][4][4];
#pragma unroll
        for (int nt = 0; nt < 4; nt++) {
            int C = wn * 32 + nt * 8 + c * 2;
            float bv0 = b1s[C], bv1 = b1s[C + 1];
#pragma unroll
            for (int mt = 0; mt < 2; mt++) {
                hacc[mt][nt][0] = bv0; hacc[mt][nt][1] = bv1;
                hacc[mt][nt][2] = bv0; hacc[mt][nt][3] = bv1;
            }
        }

        uint32_t zh[2][4], zl[2][4];
#pragma unroll
        for (int mt = 0; mt < 2; mt++) {
            LDSM_X4(zh[mt][0], zh[mt][1], zh[mt][2], zh[mt][3],
                    zBase + (uint32_t)(mt * 16) * ZSTRIDE);
            LDSM_X4(zl[mt][0], zl[mt][1], zl[mt][2], zl[mt][3],
                    zBase + (uint32_t)(mt * 16) * ZSTRIDE + 32);
        }
        uint32_t wh[4][2], wl[4][2];
#pragma unroll
        for (int j = 0; j < 2; j++) {
            uint32_t r0, r1, r2, r3;
            LDSM_X4(r0, r1, r2, r3, w1Base + (uint32_t)(j * 16) * W1STRIDE);
            wh[2*j][0] = r0;  wh[2*j][1] = r1;
            wh[2*j+1][0] = r2; wh[2*j+1][1] = r3;
            LDSM_X4(r0, r1, r2, r3, w1Base + (uint32_t)(j * 16) * W1STRIDE + 32);
            wl[2*j][0] = r0;  wl[2*j][1] = r1;
            wl[2*j+1][0] = r2; wl[2*j+1][1] = r3;
        }

#pragma unroll
        for (int mt = 0; mt < 2; mt++)
#pragma unroll
            for (int nt = 0; nt < 4; nt++) {
                MMA16816(hacc[mt][nt], zh[mt][0], zh[mt][1], zh[mt][2], zh[mt][3],
                         wh[nt][0], wh[nt][1]);
                MMA16816(hacc[mt][nt], zh[mt][0], zh[mt][1], zh[mt][2], zh[mt][3],
                         wl[nt][0], wl[nt][1]);
                MMA16816(hacc[mt][nt], zl[mt][0], zl[mt][1], zl[mt][2], zl[mt][3],
                         wh[nt][0], wh[nt][1]);
            }

        // relu + trunc-split -> sA fragments: [Hh | Hl @ +128B]
#pragma unroll
        for (int mt = 0; mt < 2; mt++)
#pragma unroll
            for (int nt = 0; nt < 4; nt++) {
                int C = wn * 32 + nt * 8 + c * 2;
                int R = wm * 32 + mt * 16 + (l >> 2);
                float v0 = fmaxf(hacc[mt][nt][0], 0.0f);
                float v1 = fmaxf(hacc[mt][nt][1], 0.0f);
                float v2 = fmaxf(hacc[mt][nt][2], 0.0f);
                float v3 = fmaxf(hacc[mt][nt][3], 0.0f);
                uint32_t hi01, lo01, hi23, lo23;
                trunc_split2(v0, v1, hi01, lo01);
                trunc_split2(v2, v3, hi23, lo23);
                *(uint32_t*)(sA + R * ASTRIDE + C * 2)             = hi01;
                *(uint32_t*)(sA + R * ASTRIDE + 128 + C * 2)       = lo01;
                *(uint32_t*)(sA + (R + 8) * ASTRIDE + C * 2)       = hi23;
                *(uint32_t*)(sA + (R + 8) * ASTRIDE + 128 + C * 2) = lo23;
            }
    }
    __syncthreads();

    // ---------------- Phase 3: main GEMM ----------------
    float acc[2][8][4];
    {
        int cb = wn * 64;
#pragma unroll
        for (int nt = 0; nt < 8; nt++) {
            int col = cb + 16 * (nt >> 1) + 4 * c + 2 * (nt & 1);
            float bv0 = b2s[col];
            float bv1 = b2s[col + 1];
#pragma unroll
            for (int mt = 0; mt < 2; mt++) {
                acc[mt][nt][0] = bv0; acc[mt][nt][1] = bv1;
                acc[mt][nt][2] = bv0; acc[mt][nt][3] = bv1;
            }
        }
    }

    uint32_t aBase = sAu + (uint32_t)(wm * 32 + (l & 15)) * ASTRIDE + ((l >> 4) << 4);
    uint32_t bRow  = (uint32_t)(wn * 64 + (l & 7) + ((l >> 4) << 3));
    uint32_t bBase = sBu + bRow * BSTRIDE + (((l >> 3) & 1) << 4);

#pragma unroll
    for (int kin = 0; kin < 4; kin++) {
        uint32_t kb = (uint32_t)(kin * 32);

        // A both halves up front (max MLP)
        uint32_t ah[2][4], al[2][4];
#pragma unroll
        for (int mt = 0; mt < 2; mt++)
            LDSM_X4(ah[mt][0], ah[mt][1], ah[mt][2], ah[mt][3],
                    aBase + (uint32_t)(mt * 16) * ASTRIDE + kb);
#pragma unroll
        for (int mt = 0; mt < 2; mt++)
            LDSM_X4(al[mt][0], al[mt][1], al[mt][2], al[mt][3],
                    aBase + (uint32_t)(mt * 16) * ASTRIDE + 128 + kb);

        uint32_t bh[8][2];
#pragma unroll
        for (int j = 0; j < 4; j++) {
            uint32_t r0, r1, r2, r3;
            LDSM_X4(r0, r1, r2, r3, bBase + (uint32_t)(j * 16) * BSTRIDE + kb);
            bh[2*j][0] = r0;  bh[2*j][1] = r1;
            bh[2*j+1][0] = r2; bh[2*j+1][1] = r3;
        }

        // term 0: Hh * Wh
#pragma unroll
        for (int mt = 0; mt < 2; mt++)
#pragma unroll
            for (int nt = 0; nt < 8; nt++)
                MMA16816(acc[mt][nt], ah[mt][0], ah[mt][1], ah[mt][2], ah[mt][3],
                         bh[nt][0], bh[nt][1]);

        uint32_t bl[8][2];
#pragma unroll
        for (int j = 0; j < 4; j++) {
            uint32_t r0, r1, r2, r3;
            LDSM_X4(r0, r1, r2, r3, bBase + (uint32_t)(j * 16) * BSTRIDE + 128 + kb);
            bl[2*j][0] = r0;  bl[2*j][1] = r1;
            bl[2*j+1][0] = r2; bl[2*j+1][1] = r3;
        }

        // term 2: Hl * Wh (bh dies after this)
#pragma unroll
        for (int mt = 0; mt < 2; mt++)
#pragma unroll
            for (int nt = 0; nt < 8; nt++)
                MMA16816(acc[mt][nt], al[mt][0], al[mt][1], al[mt][2], al[mt][3],
                         bh[nt][0], bh[nt][1]);

        // term 1: Hh * Wl
#pragma unroll
        for (int mt = 0; mt < 2; mt++)
#pragma unroll
            for (int nt = 0; nt < 8; nt++)
                MMA16816(acc[mt][nt], ah[mt][0], ah[mt][1], ah[mt][2], ah[mt][3],
                         bl[nt][0], bl[nt][1]);
    }

    // Epilogue: sigma layout -> contiguous float4 per thread
    {
        int row_l = l >> 2;
#pragma unroll
        for (int mt = 0; mt < 2; mt++) {
            int r0 = gt0 + wm * 32 + mt * 16 + row_l;
            float* base0 = out + (size_t)r0 * EMBED + e0 + wn * 64;
            float* base1 = base0 + (size_t)8 * EMBED;
#pragma unroll
            for (int g = 0; g < 4; g++) {
                float4 v0, v1;
                v0.x = acc[mt][2*g][0];   v0.y = acc[mt][2*g][1];
                v0.z = acc[mt][2*g+1][0]; v0.w = acc[mt][2*g+1][1];
                v1.x = acc[mt][2*g][2];   v1.y = acc[mt][2*g][3];
                v1.z = acc[mt][2*g+1][2]; v1.w = acc[mt][2*g+1][3];
                *(float4*)(base0 + 16 * g + 4 * c) = v0;
                *(float4*)(base1 + 16 * g + 4 * c) = v1;
            }
        }
    }
}

// ---------------------------------------------------------------------------
extern "C" void kernel_launch(void* const* d_in, const int* in_sizes, int n_in,
                              void* d_out, int out_size)
{
    const float *x = nullptr, *theta = nullptr, *W1 = nullptr,
                *b1 = nullptr, *W2 = nullptr, *b2 = nullptr;
    for (int i = 0; i < n_in; i++) {
        switch (in_sizes[i]) {
            case NTOK * EMBED: x     = (const float*)d_in[i]; break;
            case NQ:           theta = (const float*)d_in[i]; break;
            case FFN * NQ:     W1    = (const float*)d_in[i]; break;
            case FFN:          b1    = (const float*)d_in[i]; break;
            case EMBED * FFN:  W2    = (const float*)d_in[i]; break;
            case EMBED:        b2    = (const float*)d_in[i]; break;
            default: break;
        }
    }
    float* out = (float*)d_out;

    static int smem_set = 0;
    if (!smem_set) {
        cudaFuncSetAttribute(fused_ffn,
                             cudaFuncAttributeMaxDynamicSharedMemorySize,
                             SMEM_TOTAL);
        smem_set = 1;
    }

    fused_ffn<<<dim3(EMBED / NT, NTOK / MT), 256, SMEM_TOTAL>>>(
        x, theta, W1, b1, W2, b2, out);
}

// round 14
// speedup vs baseline: 2.1013x; 1.0260x over previous
#include <cuda_runtime.h>
#include <cuda_bf16.h>
#include <cstdint>

// Problem dims
#define EMBED 512
#define FFN   64
#define NQ    16
#define NTOK  65536   // 16 * 4096

// GEMM tiling
#define MT 128              // tokens per CTA
#define NT 128              // embed outputs per CTA
#define BSTRIDE 272         // B smem row stride bytes (256B data + 16B pad)
#define ZSTRIDE 80          // z tile row stride (64B data + 16B pad)
#define W1STRIDE 80

// smem offsets (no A tile anymore — H lives in registers)
#define OFF_B   0                     // 128 * 272 = 34816
#define OFF_Z   34816                 // 128 * 80  = 10240
#define OFF_W1  45056                 // 64 * 80   = 5120
#define OFF_B1  50176                 // 64 floats = 256
#define OFF_B2  50432                 // 128 floats = 512
#define SMEM_TOTAL 50944

// sigma: within a 64-col group, slot s holds W2 row sigma(s):
// s=(b5 b4 b3 b2 b1 b0) -> phys=(b5 b4 b2 b1 b3 b0)
__device__ __forceinline__ int sigma_inv(int p) {
    // inverse: (p5 p4 p3 p2 p1 p0) -> (p5 p4 p1 p3 p2 p0)
    return 16 * (p >> 4) + 8 * ((p >> 1) & 1) + 2 * ((p >> 2) & 3) + (p & 1);
}

__device__ __forceinline__ uint32_t smem_u32(const void* p) {
    uint32_t a;
    asm("{ .reg .u64 t; cvta.to.shared.u64 t, %1; cvt.u32.u64 %0, t; }"
        : "=r"(a) : "l"(p));
    return a;
}

#define LDSM_X4(r0, r1, r2, r3, addr) \
    asm volatile("ldmatrix.sync.aligned.m8n8.x4.shared.b16 {%0,%1,%2,%3}, [%4];" \
                 : "=r"(r0), "=r"(r1), "=r"(r2), "=r"(r3) : "r"(addr))

#define MMA16816(d, a0, a1, a2, a3, b0, b1) \
    asm volatile("mma.sync.aligned.m16n8k16.row.col.f32.bf16.bf16.f32 " \
                 "{%0,%1,%2,%3}, {%4,%5,%6,%7}, {%8,%9}, {%0,%1,%2,%3};" \
                 : "+f"((d)[0]), "+f"((d)[1]), "+f"((d)[2]), "+f"((d)[3]) \
                 : "r"(a0), "r"(a1), "r"(a2), "r"(a3), "r"(b0), "r"(b1))

// Exact truncation split: v = hi + lo; hi = bf16-trunc(v); lo exactly bf16.
// Packs two values with PRMT (result = {v0_hi16 lo-half, v1_hi16 hi-half}).
__device__ __forceinline__ void trunc_split2(float v0, float v1,
                                             uint32_t& hi, uint32_t& lo) {
    uint32_t u0 = __float_as_uint(v0), u1 = __float_as_uint(v1);
    float h0 = __uint_as_float(u0 & 0xFFFF0000u);
    float h1 = __uint_as_float(u1 & 0xFFFF0000u);
    float l0 = v0 - h0, l1 = v1 - h1;       // exact (Dekker truncation)
    asm("prmt.b32 %0, %1, %2, 0x7632;" : "=r"(hi) : "r"(u0), "r"(u1));
    asm("prmt.b32 %0, %1, %2, 0x7632;" : "=r"(lo)
        : "r"(__float_as_uint(l0)), "r"(__float_as_uint(l1)));
}

// ---------------------------------------------------------------------------
// Fused kernel, register-resident H. Per CTA (128 tokens x 128 e):
//  Phase 0/1: LDG x, W1, W2 (coalesced; sigma^-1 STS), biases; trunc-split
//             z -> sZ, W1 -> sW1, W2 -> sB. ONE barrier.
//  Main loop over 4 k-chunks (16 FFN cols each):
//    LDSM W1 slice -> 12 H-MMAs (z frags reg-resident) -> relu+split+PRMT
//    -> A fragments in registers -> LDSM bh -> t0,t2 MMAs -> LDSM bl -> t1.
//  Epilogue: sigma STG.128.
// ---------------------------------------------------------------------------
__global__ void __launch_bounds__(256, 2) fused_ffn(
    const float* __restrict__ x,
    const float* __restrict__ theta,
    const float* __restrict__ W1,
    const float* __restrict__ b1,
    const float* __restrict__ W2,
    const float* __restrict__ b2,
    float* __restrict__ out)
{
    extern __shared__ char dsm[];
    char*  sB  = dsm + OFF_B;
    char*  sZ  = dsm + OFF_Z;
    char*  sW1 = dsm + OFF_W1;
    float* b1s = (float*)(dsm + OFF_B1);
    float* b2s = (float*)(dsm + OFF_B2);

    uint32_t sBu  = smem_u32(sB);
    uint32_t sZu  = smem_u32(sZ);
    uint32_t sW1u = smem_u32(sW1);

    int tid = threadIdx.x;
    int e0  = blockIdx.x * NT;
    int gt0 = blockIdx.y * MT;

    // ---------------- Phase 0: global loads ----------------
    int zrow = tid >> 1, zhalf = tid & 1;            // 2 threads per token
    const float4* xp = (const float4*)(x + (size_t)(gt0 + zrow) * EMBED + zhalf * 8);
    float4 xv0 = xp[0], xv1 = xp[1];

    int w1row = tid >> 2, w1q = tid & 3;             // 4 threads per W1 row
    float4 w1v = *(const float4*)(W1 + (size_t)w1row * NQ + w1q * 4);

    int wrow = tid >> 1, whalf = tid & 1;            // coalesced W2 rows
    float4 w2v[8];
    {
        const float4* wp = (const float4*)(W2 + (size_t)(e0 + wrow) * FFN + whalf * 32);
#pragma unroll
        for (int i = 0; i < 8; i++) w2v[i] = wp[i];
    }

    if (tid < FFN) b1s[tid] = b1[tid];
    if (tid < NT)  b2s[tid] = b2[e0 + tid];

    // ---------------- Phase 1: splits into smem ----------------
    // z row: [zh k0-7 | zh k8-15 | zl k0-7 | zl k8-15]
    {
        float zf[8];
        float xf[8] = {xv0.x, xv0.y, xv0.z, xv0.w, xv1.x, xv1.y, xv1.z, xv1.w};
#pragma unroll
        for (int j = 0; j < 8; j++)
            zf[j] = __cosf(xf[j]) * __cosf(theta[zhalf * 8 + j]);
        uint32_t hi[4], lo[4];
#pragma unroll
        for (int j = 0; j < 4; j++)
            trunc_split2(zf[2*j], zf[2*j+1], hi[j], lo[j]);
        *(uint4*)(sZ + zrow * ZSTRIDE + zhalf * 16)      = make_uint4(hi[0], hi[1], hi[2], hi[3]);
        *(uint4*)(sZ + zrow * ZSTRIDE + 32 + zhalf * 16) = make_uint4(lo[0], lo[1], lo[2], lo[3]);
    }
    // W1 row: [w1h 16 bf16 (32B) | w1l (32B)]
    {
        uint32_t h0, l0, h1, l1;
        trunc_split2(w1v.x, w1v.y, h0, l0);
        trunc_split2(w1v.z, w1v.w, h1, l1);
        *(uint2*)(sW1 + w1row * W1STRIDE + w1q * 8)      = make_uint2(h0, h1);
        *(uint2*)(sW1 + w1row * W1STRIDE + 32 + w1q * 8) = make_uint2(l0, l1);
    }
    // W2 tile: slot s holds row sigma(s); loaded row wrow -> slot sigma_inv
    {
        uint32_t hi[16], lo[16];
#pragma unroll
        for (int i = 0; i < 8; i++) {
            trunc_split2(w2v[i].x, w2v[i].y, hi[2*i],   lo[2*i]);
            trunc_split2(w2v[i].z, w2v[i].w, hi[2*i+1], lo[2*i+1]);
        }
        int slot = (wrow & ~63) | sigma_inv(wrow & 63);
        char* rb = sB + slot * BSTRIDE + whalf * 64;
        *(uint4*)(rb)            = make_uint4(hi[0], hi[1], hi[2], hi[3]);
        *(uint4*)(rb + 16)       = make_uint4(hi[4], hi[5], hi[6], hi[7]);
        *(uint4*)(rb + 32)       = make_uint4(hi[8], hi[9], hi[10], hi[11]);
        *(uint4*)(rb + 48)       = make_uint4(hi[12], hi[13], hi[14], hi[15]);
        *(uint4*)(rb + 128)      = make_uint4(lo[0], lo[1], lo[2], lo[3]);
        *(uint4*)(rb + 128 + 16) = make_uint4(lo[4], lo[5], lo[6], lo[7]);
        *(uint4*)(rb + 128 + 32) = make_uint4(lo[8], lo[9], lo[10], lo[11]);
        *(uint4*)(rb + 128 + 48) = make_uint4(lo[12], lo[13], lo[14], lo[15]);
    }
    __syncthreads();

    int wid = tid >> 5, l = tid & 31;
    int wm = wid & 3;        // M block (32 token rows)
    int wn = wid >> 2;       // N block (64 e cols)
    int c  = l & 3;

    // ---------------- Pre-loop: z fragments + output accumulators ----------------
    uint32_t zh[2][4], zl[2][4];
    {
        uint32_t zBase = sZu + (uint32_t)(wm * 32 + (l & 15)) * ZSTRIDE + ((l >> 4) << 4);
#pragma unroll
        for (int mt = 0; mt < 2; mt++) {
            LDSM_X4(zh[mt][0], zh[mt][1], zh[mt][2], zh[mt][3],
                    zBase + (uint32_t)(mt * 16) * ZSTRIDE);
            LDSM_X4(zl[mt][0], zl[mt][1], zl[mt][2], zl[mt][3],
                    zBase + (uint32_t)(mt * 16) * ZSTRIDE + 32);
        }
    }

    float acc[2][8][4];
    {
        int cb = wn * 64;
#pragma unroll
        for (int nt = 0; nt < 8; nt++) {
            int col = cb + 16 * (nt >> 1) + 4 * c + 2 * (nt & 1);
            float bv0 = b2s[col];
            float bv1 = b2s[col + 1];
#pragma unroll
            for (int mt = 0; mt < 2; mt++) {
                acc[mt][nt][0] = bv0; acc[mt][nt][1] = bv1;
                acc[mt][nt][2] = bv0; acc[mt][nt][3] = bv1;
            }
        }
    }

    uint32_t w1Base = sW1u + (uint32_t)((l & 7) + ((l >> 4) << 3)) * W1STRIDE
                           + (((l >> 3) & 1) << 4);
    uint32_t bRow  = (uint32_t)(wn * 64 + (l & 7) + ((l >> 4) << 3));
    uint32_t bBase = sBu + bRow * BSTRIDE + (((l >> 3) & 1) << 4);

    // ---------------- Main loop: 4 chunks of 16 FFN cols ----------------
#pragma unroll
    for (int kin = 0; kin < 4; kin++) {
        uint32_t kb = (uint32_t)(kin * 32);

        // --- H chunk: rows wm*32..+32, cols kin*16..+16, 3-term MMA ---
        uint32_t ah[2][4], al[2][4];
        {
            uint32_t w1k = w1Base + (uint32_t)(kin * 16) * W1STRIDE;
            uint32_t w1h[2][2], w1l[2][2];
            {
                uint32_t r0, r1, r2, r3;
                LDSM_X4(r0, r1, r2, r3, w1k);
                w1h[0][0] = r0; w1h[0][1] = r1; w1h[1][0] = r2; w1h[1][1] = r3;
                LDSM_X4(r0, r1, r2, r3, w1k + 32);
                w1l[0][0] = r0; w1l[0][1] = r1; w1l[1][0] = r2; w1l[1][1] = r3;
            }

            float hacc[2][2][4];
#pragma unroll
            for (int nt = 0; nt < 2; nt++) {
                int f = kin * 16 + nt * 8 + c * 2;
                float bv0 = b1s[f], bv1 = b1s[f + 1];
#pragma unroll
                for (int mt = 0; mt < 2; mt++) {
                    hacc[mt][nt][0] = bv0; hacc[mt][nt][1] = bv1;
                    hacc[mt][nt][2] = bv0; hacc[mt][nt][3] = bv1;
                }
            }

#pragma unroll
            for (int mt = 0; mt < 2; mt++)
#pragma unroll
                for (int nt = 0; nt < 2; nt++) {
                    MMA16816(hacc[mt][nt], zh[mt][0], zh[mt][1], zh[mt][2], zh[mt][3],
                             w1h[nt][0], w1h[nt][1]);
                    MMA16816(hacc[mt][nt], zh[mt][0], zh[mt][1], zh[mt][2], zh[mt][3],
                             w1l[nt][0], w1l[nt][1]);
                    MMA16816(hacc[mt][nt], zl[mt][0], zl[mt][1], zl[mt][2], zl[mt][3],
                             w1h[nt][0], w1h[nt][1]);
                }

            // relu + split + PRMT: C fragments -> A fragments (in registers)
#pragma unroll
            for (int mt = 0; mt < 2; mt++) {
                float v0 = fmaxf(hacc[mt][0][0], 0.0f);
                float v1 = fmaxf(hacc[mt][0][1], 0.0f);
                float v2 = fmaxf(hacc[mt][0][2], 0.0f);
                float v3 = fmaxf(hacc[mt][0][3], 0.0f);
                float v4 = fmaxf(hacc[mt][1][0], 0.0f);
                float v5 = fmaxf(hacc[mt][1][1], 0.0f);
                float v6 = fmaxf(hacc[mt][1][2], 0.0f);
                float v7 = fmaxf(hacc[mt][1][3], 0.0f);
                trunc_split2(v0, v1, ah[mt][0], al[mt][0]);   // a0: rows g,   k0-7
                trunc_split2(v2, v3, ah[mt][1], al[mt][1]);   // a1: rows g+8, k0-7
                trunc_split2(v4, v5, ah[mt][2], al[mt][2]);   // a2: rows g,   k8-15
                trunc_split2(v6, v7, ah[mt][3], al[mt][3]);   // a3: rows g+8, k8-15
            }
        }

        // --- main GEMM terms ---
        uint32_t bh[8][2];
#pragma unroll
        for (int j = 0; j < 4; j++) {
            uint32_t r0, r1, r2, r3;
            LDSM_X4(r0, r1, r2, r3, bBase + (uint32_t)(j * 16) * BSTRIDE + kb);
            bh[2*j][0] = r0;  bh[2*j][1] = r1;
            bh[2*j+1][0] = r2; bh[2*j+1][1] = r3;
        }

        // term 0: Hh * Wh
#pragma unroll
        for (int mt = 0; mt < 2; mt++)
#pragma unroll
            for (int nt = 0; nt < 8; nt++)
                MMA16816(acc[mt][nt], ah[mt][0], ah[mt][1], ah[mt][2], ah[mt][3],
                         bh[nt][0], bh[nt][1]);

        // term 2: Hl * Wh (al and bh die here)
#pragma unroll
        for (int mt = 0; mt < 2; mt++)
#pragma unroll
            for (int nt = 0; nt < 8; nt++)
                MMA16816(acc[mt][nt], al[mt][0], al[mt][1], al[mt][2], al[mt][3],
                         bh[nt][0], bh[nt][1]);

        uint32_t bl[8][2];
#pragma unroll
        for (int j = 0; j < 4; j++) {
            uint32_t r0, r1, r2, r3;
            LDSM_X4(r0, r1, r2, r3, bBase + (uint32_t)(j * 16) * BSTRIDE + 128 + kb);
            bl[2*j][0] = r0;  bl[2*j][1] = r1;
            bl[2*j+1][0] = r2; bl[2*j+1][1] = r3;
        }

        // term 1: Hh * Wl
#pragma unroll
        for (int mt = 0; mt < 2; mt++)
#pragma unroll
            for (int nt = 0; nt < 8; nt++)
                MMA16816(acc[mt][nt], ah[mt][0], ah[mt][1], ah[mt][2], ah[mt][3],
                         bl[nt][0], bl[nt][1]);
    }

    // ---------------- Epilogue: sigma layout -> contiguous float4 ----------------
    {
        int row_l = l >> 2;
#pragma unroll
        for (int mt = 0; mt < 2; mt++) {
            int r0 = gt0 + wm * 32 + mt * 16 + row_l;
            float* base0 = out + (size_t)r0 * EMBED + e0 + wn * 64;
            float* base1 = base0 + (size_t)8 * EMBED;
#pragma unroll
            for (int g = 0; g < 4; g++) {
                float4 v0, v1;
                v0.x = acc[mt][2*g][0];   v0.y = acc[mt][2*g][1];
                v0.z = acc[mt][2*g+1][0]; v0.w = acc[mt][2*g+1][1];
                v1.x = acc[mt][2*g][2];   v1.y = acc[mt][2*g][3];
                v1.z = acc[mt][2*g+1][2]; v1.w = acc[mt][2*g+1][3];
                *(float4*)(base0 + 16 * g + 4 * c) = v0;
                *(float4*)(base1 + 16 * g + 4 * c) = v1;
            }
        }
    }
}

// ---------------------------------------------------------------------------
extern "C" void kernel_launch(void* const* d_in, const int* in_sizes, int n_in,
                              void* d_out, int out_size)
{
    const float *x = nullptr, *theta = nullptr, *W1 = nullptr,
                *b1 = nullptr, *W2 = nullptr, *b2 = nullptr;
    for (int i = 0; i < n_in; i++) {
        switch (in_sizes[i]) {
            case NTOK * EMBED: x     = (const float*)d_in[i]; break;
            case NQ:           theta = (const float*)d_in[i]; break;
            case FFN * NQ:     W1    = (const float*)d_in[i]; break;
            case FFN:          b1    = (const float*)d_in[i]; break;
            case EMBED * FFN:  W2    = (const float*)d_in[i]; break;
            case EMBED:        b2    = (const float*)d_in[i]; break;
            default: break;
        }
    }
    float* out = (float*)d_out;

    static int smem_set = 0;
    if (!smem_set) {
        cudaFuncSetAttribute(fused_ffn,
                             cudaFuncAttributeMaxDynamicSharedMemorySize,
                             SMEM_TOTAL);
        smem_set = 1;
    }

    fused_ffn<<<dim3(EMBED / NT, NTOK / MT), 256, SMEM_TOTAL>>>(
        x, theta, W1, b1, W2, b2, out);
}

// round 15
// speedup vs baseline: 2.2512x; 1.0713x over previous
#include <cuda_runtime.h>
#include <cuda_bf16.h>
#include <cstdint>

// Problem dims
#define EMBED 512
#define FFN   64
#define NQ    16
#define NTOK  65536   // 16 * 4096

// GEMM tiling: CTA 128 threads, tile 128 tok x 128 e, warp tile 64x64
#define MT 128
#define NT 128
#define BSTRIDE 272         // B smem row stride bytes (256B data + 16B pad)
#define ZSTRIDE 80          // z tile row stride (64B data + 16B pad)
#define W1STRIDE 80

// smem offsets (H is register-resident; no A tile)
#define OFF_B   0                     // 128 * 272 = 34816
#define OFF_Z   34816                 // 128 * 80  = 10240
#define OFF_W1  45056                 // 64 * 80   = 5120
#define OFF_B1  50176                 // 64 floats = 256
#define OFF_B2  50432                 // 128 floats = 512
#define SMEM_TOTAL 50944

// sigma: within a 64-col group, slot s holds W2 row sigma(s):
// s=(b5 b4 b3 b2 b1 b0) -> phys=(b5 b4 b2 b1 b3 b0)
__device__ __forceinline__ int sigma_inv(int p) {
    // inverse: (p5 p4 p3 p2 p1 p0) -> (p5 p4 p1 p3 p2 p0)
    return 16 * (p >> 4) + 8 * ((p >> 1) & 1) + 2 * ((p >> 2) & 3) + (p & 1);
}

__device__ __forceinline__ uint32_t smem_u32(const void* p) {
    uint32_t a;
    asm("{ .reg .u64 t; cvta.to.shared.u64 t, %1; cvt.u32.u64 %0, t; }"
        : "=r"(a) : "l"(p));
    return a;
}

#define LDSM_X4(r0, r1, r2, r3, addr) \
    asm volatile("ldmatrix.sync.aligned.m8n8.x4.shared.b16 {%0,%1,%2,%3}, [%4];" \
                 : "=r"(r0), "=r"(r1), "=r"(r2), "=r"(r3) : "r"(addr))

#define MMA16816(d, a0, a1, a2, a3, b0, b1) \
    asm volatile("mma.sync.aligned.m16n8k16.row.col.f32.bf16.bf16.f32 " \
                 "{%0,%1,%2,%3}, {%4,%5,%6,%7}, {%8,%9}, {%0,%1,%2,%3};" \
                 : "+f"((d)[0]), "+f"((d)[1]), "+f"((d)[2]), "+f"((d)[3]) \
                 : "r"(a0), "r"(a1), "r"(a2), "r"(a3), "r"(b0), "r"(b1))

// Exact truncation split: v = hi + lo; hi = bf16-trunc(v); lo exactly bf16.
__device__ __forceinline__ void trunc_split2(float v0, float v1,
                                             uint32_t& hi, uint32_t& lo) {
    uint32_t u0 = __float_as_uint(v0), u1 = __float_as_uint(v1);
    float h0 = __uint_as_float(u0 & 0xFFFF0000u);
    float h1 = __uint_as_float(u1 & 0xFFFF0000u);
    float l0 = v0 - h0, l1 = v1 - h1;       // exact (Dekker truncation)
    asm("prmt.b32 %0, %1, %2, 0x7632;" : "=r"(hi) : "r"(u0), "r"(u1));
    asm("prmt.b32 %0, %1, %2, 0x7632;" : "=r"(lo)
        : "r"(__float_as_uint(l0)), "r"(__float_as_uint(l1)));
}

// ---------------------------------------------------------------------------
// Fused kernel, register-resident H, 64x64 warp tiles (4 warps, 255-reg budget).
// ---------------------------------------------------------------------------
__global__ void __launch_bounds__(128, 2) fused_ffn(
    const float* __restrict__ x,
    const float* __restrict__ theta,
    const float* __restrict__ W1,
    const float* __restrict__ b1,
    const float* __restrict__ W2,
    const float* __restrict__ b2,
    float* __restrict__ out)
{
    extern __shared__ char dsm[];
    char*  sB  = dsm + OFF_B;
    char*  sZ  = dsm + OFF_Z;
    char*  sW1 = dsm + OFF_W1;
    float* b1s = (float*)(dsm + OFF_B1);
    float* b2s = (float*)(dsm + OFF_B2);

    uint32_t sBu  = smem_u32(sB);
    uint32_t sZu  = smem_u32(sZ);
    uint32_t sW1u = smem_u32(sW1);

    int tid = threadIdx.x;
    int e0  = blockIdx.x * NT;
    int gt0 = blockIdx.y * MT;

    // ---------------- Phase 0/1: loads + splits into smem ----------------
    // z: one thread per token row (all 16 q-features)
    {
        const float4* xp = (const float4*)(x + (size_t)(gt0 + tid) * EMBED);
        float4 xv[4];
#pragma unroll
        for (int i = 0; i < 4; i++) xv[i] = xp[i];
        float zf[16];
        const float* xf = (const float*)xv;
#pragma unroll
        for (int j = 0; j < 16; j++)
            zf[j] = __cosf(xf[j]) * __cosf(theta[j]);
        uint32_t hi[8], lo[8];
#pragma unroll
        for (int j = 0; j < 8; j++)
            trunc_split2(zf[2*j], zf[2*j+1], hi[j], lo[j]);
        char* zr = sZ + tid * ZSTRIDE;
        *(uint4*)(zr)      = make_uint4(hi[0], hi[1], hi[2], hi[3]);
        *(uint4*)(zr + 16) = make_uint4(hi[4], hi[5], hi[6], hi[7]);
        *(uint4*)(zr + 32) = make_uint4(lo[0], lo[1], lo[2], lo[3]);
        *(uint4*)(zr + 48) = make_uint4(lo[4], lo[5], lo[6], lo[7]);
    }
    // W1: 2 threads per row (8 floats each)
    {
        int row = tid >> 1, q = tid & 1;
        const float4* wp = (const float4*)(W1 + (size_t)row * NQ + q * 8);
        float4 va = wp[0], vb = wp[1];
        uint32_t h[4], l[4];
        trunc_split2(va.x, va.y, h[0], l[0]);
        trunc_split2(va.z, va.w, h[1], l[1]);
        trunc_split2(vb.x, vb.y, h[2], l[2]);
        trunc_split2(vb.z, vb.w, h[3], l[3]);
        char* rb = sW1 + row * W1STRIDE + q * 16;
        *(uint4*)(rb)      = make_uint4(h[0], h[1], h[2], h[3]);
        *(uint4*)(rb + 32) = make_uint4(l[0], l[1], l[2], l[3]);
    }
    // W2: one thread per row (coalesced), sigma^-1 slot, two 32-float halves
    {
        int wrow = tid;
        int slot = (wrow & ~63) | sigma_inv(wrow & 63);
        char* rb = sB + slot * BSTRIDE;
        const float4* wp = (const float4*)(W2 + (size_t)(e0 + wrow) * FFN);
#pragma unroll
        for (int half = 0; half < 2; half++) {
            float4 v[8];
#pragma unroll
            for (int i = 0; i < 8; i++) v[i] = wp[half * 8 + i];
            uint32_t hi[16], lo[16];
#pragma unroll
            for (int i = 0; i < 8; i++) {
                trunc_split2(v[i].x, v[i].y, hi[2*i],   lo[2*i]);
                trunc_split2(v[i].z, v[i].w, hi[2*i+1], lo[2*i+1]);
            }
            char* dh = rb + half * 64;
            char* dl = rb + 128 + half * 64;
#pragma unroll
            for (int i = 0; i < 4; i++) {
                *(uint4*)(dh + i * 16) = make_uint4(hi[4*i], hi[4*i+1], hi[4*i+2], hi[4*i+3]);
                *(uint4*)(dl + i * 16) = make_uint4(lo[4*i], lo[4*i+1], lo[4*i+2], lo[4*i+3]);
            }
        }
    }
    if (tid < FFN) b1s[tid] = b1[tid];
    b2s[tid] = b2[e0 + tid];
    __syncthreads();

    int wid = tid >> 5, l = tid & 31;
    int wm = wid & 1;        // M block (64 token rows)
    int wn = wid >> 1;       // N block (64 e cols)
    int c  = l & 3;

    // ---------------- Pre-loop: z fragments + output accumulators ----------------
    uint32_t zh[4][4], zl[4][4];
    {
        uint32_t zBase = sZu + (uint32_t)(wm * 64 + (l & 15)) * ZSTRIDE + ((l >> 4) << 4);
#pragma unroll
        for (int mt = 0; mt < 4; mt++) {
            LDSM_X4(zh[mt][0], zh[mt][1], zh[mt][2], zh[mt][3],
                    zBase + (uint32_t)(mt * 16) * ZSTRIDE);
            LDSM_X4(zl[mt][0], zl[mt][1], zl[mt][2], zl[mt][3],
                    zBase + (uint32_t)(mt * 16) * ZSTRIDE + 32);
        }
    }

    float acc[4][8][4];
    {
        int cb = wn * 64;
#pragma unroll
        for (int nt = 0; nt < 8; nt++) {
            int col = cb + 16 * (nt >> 1) + 4 * c + 2 * (nt & 1);
            float bv0 = b2s[col];
            float bv1 = b2s[col + 1];
#pragma unroll
            for (int mt = 0; mt < 4; mt++) {
                acc[mt][nt][0] = bv0; acc[mt][nt][1] = bv1;
                acc[mt][nt][2] = bv0; acc[mt][nt][3] = bv1;
            }
        }
    }

    uint32_t w1Base = sW1u + (uint32_t)((l & 7) + ((l >> 4) << 3)) * W1STRIDE
                           + (((l >> 3) & 1) << 4);
    uint32_t bRow  = (uint32_t)(wn * 64 + (l & 7) + ((l >> 4) << 3));
    uint32_t bBase = sBu + bRow * BSTRIDE + (((l >> 3) & 1) << 4);

    // ---------------- Main loop: 4 chunks of 16 FFN cols ----------------
#pragma unroll
    for (int kin = 0; kin < 4; kin++) {
        uint32_t kb = (uint32_t)(kin * 32);

        // --- H chunk: rows wm*64..+64, cols kin*16..+16, 3-term MMA ---
        uint32_t ah[4][4], al[4][4];
        {
            uint32_t w1k = w1Base + (uint32_t)(kin * 16) * W1STRIDE;
            uint32_t w1h[2][2], w1l[2][2];
            {
                uint32_t r0, r1, r2, r3;
                LDSM_X4(r0, r1, r2, r3, w1k);
                w1h[0][0] = r0; w1h[0][1] = r1; w1h[1][0] = r2; w1h[1][1] = r3;
                LDSM_X4(r0, r1, r2, r3, w1k + 32);
                w1l[0][0] = r0; w1l[0][1] = r1; w1l[1][0] = r2; w1l[1][1] = r3;
            }

            float hacc[4][2][4];
#pragma unroll
            for (int nt = 0; nt < 2; nt++) {
                int f = kin * 16 + nt * 8 + c * 2;
                float bv0 = b1s[f], bv1 = b1s[f + 1];
#pragma unroll
                for (int mt = 0; mt < 4; mt++) {
                    hacc[mt][nt][0] = bv0; hacc[mt][nt][1] = bv1;
                    hacc[mt][nt][2] = bv0; hacc[mt][nt][3] = bv1;
                }
            }

#pragma unroll
            for (int mt = 0; mt < 4; mt++)
#pragma unroll
                for (int nt = 0; nt < 2; nt++) {
                    MMA16816(hacc[mt][nt], zh[mt][0], zh[mt][1], zh[mt][2], zh[mt][3],
                             w1h[nt][0], w1h[nt][1]);
                    MMA16816(hacc[mt][nt], zh[mt][0], zh[mt][1], zh[mt][2], zh[mt][3],
                             w1l[nt][0], w1l[nt][1]);
                    MMA16816(hacc[mt][nt], zl[mt][0], zl[mt][1], zl[mt][2], zl[mt][3],
                             w1h[nt][0], w1h[nt][1]);
                }

            // relu + split + PRMT: C fragments -> A fragments (registers)
#pragma unroll
            for (int mt = 0; mt < 4; mt++) {
                float v0 = fmaxf(hacc[mt][0][0], 0.0f);
                float v1 = fmaxf(hacc[mt][0][1], 0.0f);
                float v2 = fmaxf(hacc[mt][0][2], 0.0f);
                float v3 = fmaxf(hacc[mt][0][3], 0.0f);
                float v4 = fmaxf(hacc[mt][1][0], 0.0f);
                float v5 = fmaxf(hacc[mt][1][1], 0.0f);
                float v6 = fmaxf(hacc[mt][1][2], 0.0f);
                float v7 = fmaxf(hacc[mt][1][3], 0.0f);
                trunc_split2(v0, v1, ah[mt][0], al[mt][0]);   // rows g,   k0-7
                trunc_split2(v2, v3, ah[mt][1], al[mt][1]);   // rows g+8, k0-7
                trunc_split2(v4, v5, ah[mt][2], al[mt][2]);   // rows g,   k8-15
                trunc_split2(v6, v7, ah[mt][3], al[mt][3]);   // rows g+8, k8-15
            }
        }

        // --- main GEMM terms ---
        uint32_t bh[8][2];
#pragma unroll
        for (int j = 0; j < 4; j++) {
            uint32_t r0, r1, r2, r3;
            LDSM_X4(r0, r1, r2, r3, bBase + (uint32_t)(j * 16) * BSTRIDE + kb);
            bh[2*j][0] = r0;  bh[2*j][1] = r1;
            bh[2*j+1][0] = r2; bh[2*j+1][1] = r3;
        }

        // term 0: Hh * Wh
#pragma unroll
        for (int mt = 0; mt < 4; mt++)
#pragma unroll
            for (int nt = 0; nt < 8; nt++)
                MMA16816(acc[mt][nt], ah[mt][0], ah[mt][1], ah[mt][2], ah[mt][3],
                         bh[nt][0], bh[nt][1]);

        // term 2: Hl * Wh
#pragma unroll
        for (int mt = 0; mt < 4; mt++)
#pragma unroll
            for (int nt = 0; nt < 8; nt++)
                MMA16816(acc[mt][nt], al[mt][0], al[mt][1], al[mt][2], al[mt][3],
                         bh[nt][0], bh[nt][1]);

        uint32_t bl[8][2];
#pragma unroll
        for (int j = 0; j < 4; j++) {
            uint32_t r0, r1, r2, r3;
            LDSM_X4(r0, r1, r2, r3, bBase + (uint32_t)(j * 16) * BSTRIDE + 128 + kb);
            bl[2*j][0] = r0;  bl[2*j][1] = r1;
            bl[2*j+1][0] = r2; bl[2*j+1][1] = r3;
        }

        // term 1: Hh * Wl
#pragma unroll
        for (int mt = 0; mt < 4; mt++)
#pragma unroll
            for (int nt = 0; nt < 8; nt++)
                MMA16816(acc[mt][nt], ah[mt][0], ah[mt][1], ah[mt][2], ah[mt][3],
                         bl[nt][0], bl[nt][1]);
    }

    // ---------------- Epilogue: sigma layout -> contiguous float4 ----------------
    {
        int row_l = l >> 2;
#pragma unroll
        for (int mt = 0; mt < 4; mt++) {
            int r0 = gt0 + wm * 64 + mt * 16 + row_l;
            float* base0 = out + (size_t)r0 * EMBED + e0 + wn * 64;
            float* base1 = base0 + (size_t)8 * EMBED;
#pragma unroll
            for (int g = 0; g < 4; g++) {
                float4 v0, v1;
                v0.x = acc[mt][2*g][0];   v0.y = acc[mt][2*g][1];
                v0.z = acc[mt][2*g+1][0]; v0.w = acc[mt][2*g+1][1];
                v1.x = acc[mt][2*g][2];   v1.y = acc[mt][2*g][3];
                v1.z = acc[mt][2*g+1][2]; v1.w = acc[mt][2*g+1][3];
                *(float4*)(base0 + 16 * g + 4 * c) = v0;
                *(float4*)(base1 + 16 * g + 4 * c) = v1;
            }
        }
    }
}

// ---------------------------------------------------------------------------
extern "C" void kernel_launch(void* const* d_in, const int* in_sizes, int n_in,
                              void* d_out, int out_size)
{
    const float *x = nullptr, *theta = nullptr, *W1 = nullptr,
                *b1 = nullptr, *W2 = nullptr, *b2 = nullptr;
    for (int i = 0; i < n_in; i++) {
        switch (in_sizes[i]) {
            case NTOK * EMBED: x     = (const float*)d_in[i]; break;
            case NQ:           theta = (const float*)d_in[i]; break;
            case FFN * NQ:     W1    = (const float*)d_in[i]; break;
            case FFN:          b1    = (const float*)d_in[i]; break;
            case EMBED * FFN:  W2    = (const float*)d_in[i]; break;
            case EMBED:        b2    = (const float*)d_in[i]; break;
            default: break;
        }
    }
    float* out = (float*)d_out;

    static int smem_set = 0;
    if (!smem_set) {
        cudaFuncSetAttribute(fused_ffn,
                             cudaFuncAttributeMaxDynamicSharedMemorySize,
                             SMEM_TOTAL);
        smem_set = 1;
    }

    fused_ffn<<<dim3(EMBED / NT, NTOK / MT), 128, SMEM_TOTAL>>>(
        x, theta, W1, b1, W2, b2, out);
}